// round 1
// baseline (speedup 1.0000x reference)
#include <cuda_runtime.h>
#include <math.h>

#define Bb 2
#define Ll 2048
#define Mm 2048
#define Dd 1024
#define Hh 16
#define DHh 64
#define FFf 4096
#define WINW 64
#define RB (Bb*Ll)      // 4096 rows for x-derived activations
#define SEG (RB*Dd)     // 4194304 floats

// Scratch: 7 segments of [4096,1024] + 1 of [4096,4096]
__device__ float g_scratch[(size_t)SEG*7 + (size_t)RB*FFf];

// ---------------------------------------------------------------------------
// GEMM: C[R,N] = A[R,K] @ W[K,N] + bias[N], optional exact GELU epilogue.
// 64x64 tile, BK=16, 256 threads, 4x4 per thread.
// ---------------------------------------------------------------------------
template<bool GELU>
__global__ __launch_bounds__(256) void gemm_bias_kernel(
    const float* __restrict__ A, const float* __restrict__ Wm,
    const float* __restrict__ bias, float* __restrict__ C,
    int K, int N)
{
    __shared__ __align__(16) float As[16][68];   // [k][m], padded (272B rows, 16B aligned)
    __shared__ __align__(16) float Bs[16][64];   // [k][n]

    const int tx = threadIdx.x, ty = threadIdx.y;
    const int tid = ty * 16 + tx;
    const int row0 = blockIdx.y * 64, col0 = blockIdx.x * 64;

    float c[4][4] = {};

    // A loader: one float4 per thread per k-step: m = tid/4, k4 = (tid%4)*4
    const int am = tid >> 2, ak4 = (tid & 3) << 2;
    // B loader: k = tid/16, n4 = (tid%16)*4
    const int bk = tid >> 4, bn4 = (tid & 15) << 2;

    const float* Ap = A + (size_t)(row0 + am) * K + ak4;
    const float* Bp = Wm + (size_t)bk * N + col0 + bn4;

    for (int k0 = 0; k0 < K; k0 += 16) {
        float4 av = *(const float4*)(Ap + k0);
        As[ak4 + 0][am] = av.x;
        As[ak4 + 1][am] = av.y;
        As[ak4 + 2][am] = av.z;
        As[ak4 + 3][am] = av.w;
        *(float4*)&Bs[bk][bn4] = *(const float4*)(Bp + (size_t)k0 * N);
        __syncthreads();

        #pragma unroll
        for (int k = 0; k < 16; k++) {
            float4 a = *(const float4*)&As[k][ty << 2];
            float4 b = *(const float4*)&Bs[k][tx << 2];
            c[0][0] += a.x * b.x; c[0][1] += a.x * b.y; c[0][2] += a.x * b.z; c[0][3] += a.x * b.w;
            c[1][0] += a.y * b.x; c[1][1] += a.y * b.y; c[1][2] += a.y * b.z; c[1][3] += a.y * b.w;
            c[2][0] += a.z * b.x; c[2][1] += a.z * b.y; c[2][2] += a.z * b.z; c[2][3] += a.z * b.w;
            c[3][0] += a.w * b.x; c[3][1] += a.w * b.y; c[3][2] += a.w * b.z; c[3][3] += a.w * b.w;
        }
        __syncthreads();
    }

    const int cn = col0 + (tx << 2);
    const float4 bb = *(const float4*)&bias[cn];
    #pragma unroll
    for (int i = 0; i < 4; i++) {
        float4 o;
        o.x = c[i][0] + bb.x;
        o.y = c[i][1] + bb.y;
        o.z = c[i][2] + bb.z;
        o.w = c[i][3] + bb.w;
        if (GELU) {
            o.x = 0.5f * o.x * (1.0f + erff(o.x * 0.70710678118654752f));
            o.y = 0.5f * o.y * (1.0f + erff(o.y * 0.70710678118654752f));
            o.z = 0.5f * o.z * (1.0f + erff(o.z * 0.70710678118654752f));
            o.w = 0.5f * o.w * (1.0f + erff(o.w * 0.70710678118654752f));
        }
        *(float4*)&C[(size_t)(row0 + (ty << 2) + i) * N + cn] = o;
    }
}

// ---------------------------------------------------------------------------
// Attention. q:[B,Lq=L,D] (head h -> cols h*64..), k/v:[B,Lk,D].
// Block: 256 threads, 16 queries; key tiles of 64 with online softmax.
// WINDOWED: causal local window W=64 + ALiBi bias slope_h*(j-i).
// ---------------------------------------------------------------------------
template<bool WINDOWED>
__global__ __launch_bounds__(256) void attn_kernel(
    const float* __restrict__ q, const float* __restrict__ k,
    const float* __restrict__ v, float* __restrict__ out, int Lk)
{
    __shared__ __align__(16) float q_s[16][64];
    __shared__ float K_s[64 * 65];                 // padded rows: conflict-free score reads
    __shared__ __align__(16) float V_s[64 * 64];
    __shared__ float P_s[16 * 64];

    const int tid = threadIdx.x;
    const int b = blockIdx.y >> 4, h = blockIdx.y & 15;
    const int q0 = blockIdx.x * 16;

    const float* qb = q + (size_t)(b * Ll + q0) * Dd + h * DHh;
    const float* kb = k + (size_t)b * Lk * Dd + h * DHh;
    const float* vb = v + (size_t)b * Lk * Dd + h * DHh;

    // load 16x64 query tile (one float4 per thread)
    {
        int ltq = tid >> 4, ld4 = (tid & 15) << 2;
        *(float4*)&q_s[ltq][ld4] = *(const float4*)(qb + (size_t)ltq * Dd + ld4);
    }

    const int tq = tid >> 4, tx = tid & 15;
    const int i = q0 + tq;
    const float slope = WINDOWED ? exp2f(-0.5f * (float)(h + 1)) : 0.0f;

    float m = -3.4e38f, l = 0.0f;
    float o0 = 0.f, o1 = 0.f, o2 = 0.f, o3 = 0.f;

    int t0 = 0, t1 = Lk / 64 - 1;
    if (WINDOWED) {
        int js = q0 - (WINW - 1); if (js < 0) js = 0;
        t0 = js >> 6;
        t1 = (q0 + 15) >> 6;
    }
    __syncthreads();

    for (int t = t0; t <= t1; t++) {
        // load K tile (scalar, padded) and V tile (float4)
        for (int idx = tid; idx < 4096; idx += 256) {
            int kk = idx >> 6, d = idx & 63;
            K_s[kk * 65 + d] = kb[(size_t)((t << 6) + kk) * Dd + d];
        }
        for (int f = tid; f < 1024; f += 256) {
            int kk = f >> 4, d4 = (f & 15) << 2;
            *(float4*)&V_s[kk * 64 + d4] = *(const float4*)(vb + (size_t)((t << 6) + kk) * Dd + d4);
        }
        __syncthreads();

        // scores: each thread computes 4 keys (tx, tx+16, tx+32, tx+48) for its query
        float sv[4];
        #pragma unroll
        for (int ii = 0; ii < 4; ii++) {
            int kk = tx + (ii << 4);
            int j = (t << 6) + kk;
            const float* kr = &K_s[kk * 65];
            float s = 0.f;
            #pragma unroll
            for (int d = 0; d < 64; d++) s += q_s[tq][d] * kr[d];
            s *= 0.125f;   // 1/sqrt(64)
            if (WINDOWED) {
                s += slope * (float)(j - i);
                if (j > i || (i - j) >= WINW) s = -3.4e38f;
            }
            sv[ii] = s;
        }

        // row max across the 16 lanes of this query
        float mt = fmaxf(fmaxf(sv[0], sv[1]), fmaxf(sv[2], sv[3]));
        #pragma unroll
        for (int off = 8; off >= 1; off >>= 1)
            mt = fmaxf(mt, __shfl_xor_sync(0xffffffffu, mt, off));

        float mnew = fmaxf(m, mt);
        float corr, p0, p1, p2, p3;
        if (mnew < -1e37f) {           // whole tile masked for this row
            corr = 1.f; p0 = p1 = p2 = p3 = 0.f;
        } else {
            corr = __expf(m - mnew);   // m==-3.4e38 -> 0
            p0 = __expf(sv[0] - mnew);
            p1 = __expf(sv[1] - mnew);
            p2 = __expf(sv[2] - mnew);
            p3 = __expf(sv[3] - mnew);
        }
        float tl = p0 + p1 + p2 + p3;
        #pragma unroll
        for (int off = 8; off >= 1; off >>= 1)
            tl += __shfl_xor_sync(0xffffffffu, tl, off);

        l = l * corr + tl;
        m = mnew;
        o0 *= corr; o1 *= corr; o2 *= corr; o3 *= corr;

        P_s[tq * 64 + tx     ] = p0;
        P_s[tq * 64 + tx + 16] = p1;
        P_s[tq * 64 + tx + 32] = p2;
        P_s[tq * 64 + tx + 48] = p3;
        __syncthreads();

        // accumulate: thread owns dims tx*4..tx*4+3 of its query
        #pragma unroll
        for (int kk = 0; kk < 64; kk++) {
            float pp = P_s[tq * 64 + kk];
            float4 vv = *(const float4*)&V_s[kk * 64 + (tx << 2)];
            o0 += pp * vv.x; o1 += pp * vv.y; o2 += pp * vv.z; o3 += pp * vv.w;
        }
        __syncthreads();
    }

    float inv = 1.0f / l;
    float4 r;
    r.x = o0 * inv; r.y = o1 * inv; r.z = o2 * inv; r.w = o3 * inv;
    *(float4*)(out + (size_t)(b * Ll + i) * Dd + h * DHh + (tx << 2)) = r;
}

// ---------------------------------------------------------------------------
// out = LayerNorm(a + bres) * g + be, row-wise over D=1024. Block 256 threads.
// ---------------------------------------------------------------------------
__global__ __launch_bounds__(256) void add_ln_kernel(
    const float* __restrict__ a, const float* __restrict__ bres,
    const float* __restrict__ g, const float* __restrict__ be,
    float* __restrict__ out)
{
    const int row = blockIdx.x;
    const int tid = threadIdx.x;
    const int d4 = tid << 2;

    float4 va = *(const float4*)(a + (size_t)row * Dd + d4);
    float4 vb = *(const float4*)(bres + (size_t)row * Dd + d4);
    float x0 = va.x + vb.x, x1 = va.y + vb.y, x2 = va.z + vb.z, x3 = va.w + vb.w;

    float s = x0 + x1 + x2 + x3;
    float ss = x0 * x0 + x1 * x1 + x2 * x2 + x3 * x3;

    #pragma unroll
    for (int off = 16; off >= 1; off >>= 1) {
        s  += __shfl_down_sync(0xffffffffu, s,  off);
        ss += __shfl_down_sync(0xffffffffu, ss, off);
    }
    __shared__ float rs[8], rss[8];
    __shared__ float s_mu, s_rstd;
    if ((tid & 31) == 0) { rs[tid >> 5] = s; rss[tid >> 5] = ss; }
    __syncthreads();
    if (tid == 0) {
        float S = 0.f, SS = 0.f;
        #pragma unroll
        for (int w = 0; w < 8; w++) { S += rs[w]; SS += rss[w]; }
        float mu = S * (1.0f / Dd);
        float var = SS * (1.0f / Dd) - mu * mu;
        s_mu = mu;
        s_rstd = rsqrtf(var + 1e-5f);
    }
    __syncthreads();
    float mu = s_mu, rstd = s_rstd;

    float4 gg = *(const float4*)(g + d4);
    float4 bb = *(const float4*)(be + d4);
    float4 o;
    o.x = (x0 - mu) * rstd * gg.x + bb.x;
    o.y = (x1 - mu) * rstd * gg.y + bb.y;
    o.z = (x2 - mu) * rstd * gg.z + bb.z;
    o.w = (x3 - mu) * rstd * gg.w + bb.w;
    *(float4*)(out + (size_t)row * Dd + d4) = o;
}

// ---------------------------------------------------------------------------
extern "C" void kernel_launch(void* const* d_in, const int* in_sizes, int n_in,
                              void* d_out, int out_size)
{
    const float* x   = (const float*)d_in[0];
    const float* mem = (const float*)d_in[1];

    const float *swq, *sbq, *swk, *sbk, *swv, *sbv, *swo, *sbo;
    const float *cwq, *cbq, *cwk, *cbk, *cwv, *cbv, *cwo, *cbo;
    const float *w1, *b1, *w2, *b2, *g1, *be1, *g2, *be2, *g3, *be3;

    // Disambiguate input ordering at runtime:
    // signature order -> in_sizes[3] == 1024 (sbq); dict order -> 1048576 (swk)
    if (in_sizes[3] == Dd) {
        swq=(const float*)d_in[2];  sbq=(const float*)d_in[3];
        swk=(const float*)d_in[4];  sbk=(const float*)d_in[5];
        swv=(const float*)d_in[6];  sbv=(const float*)d_in[7];
        swo=(const float*)d_in[8];  sbo=(const float*)d_in[9];
        cwq=(const float*)d_in[10]; cbq=(const float*)d_in[11];
        cwk=(const float*)d_in[12]; cbk=(const float*)d_in[13];
        cwv=(const float*)d_in[14]; cbv=(const float*)d_in[15];
        cwo=(const float*)d_in[16]; cbo=(const float*)d_in[17];
        w1=(const float*)d_in[18];  b1=(const float*)d_in[19];
        w2=(const float*)d_in[20];  b2=(const float*)d_in[21];
        g1=(const float*)d_in[22];  be1=(const float*)d_in[23];
        g2=(const float*)d_in[24];  be2=(const float*)d_in[25];
        g3=(const float*)d_in[26];  be3=(const float*)d_in[27];
    } else {
        swq=(const float*)d_in[2];  swk=(const float*)d_in[3];
        swv=(const float*)d_in[4];  swo=(const float*)d_in[5];
        sbq=(const float*)d_in[6];  sbk=(const float*)d_in[7];
        sbv=(const float*)d_in[8];  sbo=(const float*)d_in[9];
        cwq=(const float*)d_in[10]; cwk=(const float*)d_in[11];
        cwv=(const float*)d_in[12]; cwo=(const float*)d_in[13];
        cbq=(const float*)d_in[14]; cbk=(const float*)d_in[15];
        cbv=(const float*)d_in[16]; cbo=(const float*)d_in[17];
        w1=(const float*)d_in[18];  b1=(const float*)d_in[19];
        w2=(const float*)d_in[20];  b2=(const float*)d_in[21];
        g1=(const float*)d_in[22];  g2=(const float*)d_in[23];
        g3=(const float*)d_in[24];
        be1=(const float*)d_in[25]; be2=(const float*)d_in[26];
        be3=(const float*)d_in[27];
    }

    float* s = nullptr;
    cudaGetSymbolAddress((void**)&s, g_scratch);
    float* bq   = s;
    float* bk   = s + (size_t)SEG;
    float* bv   = s + (size_t)SEG * 2;
    float* batt = s + (size_t)SEG * 3;
    float* btmp = s + (size_t)SEG * 4;
    float* bx1  = s + (size_t)SEG * 5;
    float* bx2  = s + (size_t)SEG * 6;
    float* bff  = s + (size_t)SEG * 7;

    dim3 blk(16, 16);
    dim3 gP(Dd / 64, RB / 64);    // projections: N=1024
    dim3 gF1(FFf / 64, RB / 64);  // FFN up:      N=4096
    dim3 gAttn(Ll / 16, Bb * Hh);

    // ---- self-attention ----
    gemm_bias_kernel<false><<<gP, blk>>>(x, swq, sbq, bq, Dd, Dd);
    gemm_bias_kernel<false><<<gP, blk>>>(x, swk, sbk, bk, Dd, Dd);
    gemm_bias_kernel<false><<<gP, blk>>>(x, swv, sbv, bv, Dd, Dd);
    attn_kernel<true><<<gAttn, 256>>>(bq, bk, bv, batt, Ll);
    gemm_bias_kernel<false><<<gP, blk>>>(batt, swo, sbo, btmp, Dd, Dd);
    add_ln_kernel<<<RB, 256>>>(x, btmp, g1, be1, bx1);

    // ---- cross-attention ----
    gemm_bias_kernel<false><<<gP, blk>>>(bx1, cwq, cbq, bq, Dd, Dd);
    gemm_bias_kernel<false><<<gP, blk>>>(mem, cwk, cbk, bk, Dd, Dd);
    gemm_bias_kernel<false><<<gP, blk>>>(mem, cwv, cbv, bv, Dd, Dd);
    attn_kernel<false><<<gAttn, 256>>>(bq, bk, bv, batt, Mm);
    gemm_bias_kernel<false><<<gP, blk>>>(batt, cwo, cbo, btmp, Dd, Dd);
    add_ln_kernel<<<RB, 256>>>(bx1, btmp, g2, be2, bx2);

    // ---- FFN ----
    gemm_bias_kernel<true><<<gF1, blk>>>(bx2, w1, b1, bff, Dd, FFf);
    gemm_bias_kernel<false><<<gP, blk>>>(bff, w2, b2, btmp, FFf, Dd);
    add_ln_kernel<<<RB, 256>>>(bx2, btmp, g3, be3, (float*)d_out);
}

// round 3
// speedup vs baseline: 1.7556x; 1.7556x over previous
#include <cuda_runtime.h>
#include <cuda_fp16.h>
#include <cstdint>
#include <math.h>

typedef unsigned int u32;

#define Bb 2
#define Ll 2048
#define Mm 2048
#define Dd 1024
#define Hh 16
#define DHh 64
#define FFf 4096
#define WINW 64
#define RB (Bb*Ll)      // 4096 rows for x-derived activations
#define SEG (RB*Dd)     // 4194304 floats

// Scratch: 7 segments of [4096,1024] + 1 of [4096,4096]
__device__ float g_scratch[(size_t)SEG*7 + (size_t)RB*FFf];

// ---------------------------------------------------------------------------
// Tensor-core GEMM: C[R,N] = A[R,K] @ W[K,N] + bias[N], optional exact GELU.
// fp32 in gmem, converted to fp16 in smem loaders, fp32 accumulate via
// mma.sync.m16n8k16. Block tile 128x128xBK32, 8 warps (2x4), warp tile 64x32.
// ---------------------------------------------------------------------------
__device__ __forceinline__ u32 pkh2(float x, float y) {
    __half2 h = __floats2half2_rn(x, y);
    return *(u32*)&h;
}

template<bool GELU>
__global__ __launch_bounds__(256, 2) void hgemm_kernel(
    const float* __restrict__ A, const float* __restrict__ Wm,
    const float* __restrict__ bias, float* __restrict__ C,
    int K, int N)
{
    // A: 128 rows x 64B (32 halfs), chunk(16B) swizzle c' = (c + (r>>1)) & 3
    // B: 32 rows x 256B (128 halfs), chunk swizzle c' = c ^ (r & 7)
    __shared__ __align__(16) unsigned char smem_buf[128*64 + 32*256];
    unsigned char* Asm = smem_buf;
    unsigned char* Bsm = smem_buf + 128*64;

    const int tid = threadIdx.x;
    const int lane = tid & 31, wid = tid >> 5;
    const int warp_m = wid >> 2, warp_n = wid & 3;   // 2 x 4 warps
    const int row0 = blockIdx.y * 128, col0 = blockIdx.x * 128;

    const u32 sA = (u32)__cvta_generic_to_shared(Asm);
    const u32 sB = (u32)__cvta_generic_to_shared(Bsm);

    float acc[4][4][4];
    #pragma unroll
    for (int i = 0; i < 4; i++)
        #pragma unroll
        for (int j = 0; j < 4; j++)
            #pragma unroll
            for (int q = 0; q < 4; q++) acc[i][j][q] = 0.f;

    // A loader: row ar = tid/2, k-half akh = tid%2 (16 floats each)
    const int ar = tid >> 1, akh = tid & 1;
    // B loader: k-row br = tid/8, n-chunk bnh = tid%8 (16 floats each)
    const int br = tid >> 3, bnh = tid & 7;

    const float* Ap = A + (size_t)(row0 + ar) * K + akh * 16;
    const float* Bp = Wm + (size_t)br * N + col0 + bnh * 16;

    // precomputed smem store addresses
    const int ac0 = akh * 2;
    const u32 aAddr0 = sA + ar * 64 + (((ac0    ) + (ar >> 1)) & 3) * 16;
    const u32 aAddr1 = sA + ar * 64 + (((ac0 + 1) + (ar >> 1)) & 3) * 16;
    const int bc0 = bnh * 2;
    const u32 bAddr0 = sB + br * 256 + ((bc0      ^ (br & 7))) * 16;
    const u32 bAddr1 = sB + br * 256 + (((bc0 + 1) ^ (br & 7))) * 16;

    for (int k0 = 0; k0 < K; k0 += 32) {
        // gmem loads (fp32) — issued before the barrier to overlap prior mma
        const float* ap = Ap + k0;
        float4 av0 = *(const float4*)(ap);
        float4 av1 = *(const float4*)(ap + 4);
        float4 av2 = *(const float4*)(ap + 8);
        float4 av3 = *(const float4*)(ap + 12);
        const float* bp = Bp + (size_t)k0 * N;
        float4 bv0 = *(const float4*)(bp);
        float4 bv1 = *(const float4*)(bp + 4);
        float4 bv2 = *(const float4*)(bp + 8);
        float4 bv3 = *(const float4*)(bp + 12);

        __syncthreads();   // previous iteration's ldmatrix done

        u32 wx, wy, wz, ww;
        wx = pkh2(av0.x, av0.y); wy = pkh2(av0.z, av0.w);
        wz = pkh2(av1.x, av1.y); ww = pkh2(av1.z, av1.w);
        asm volatile("st.shared.v4.b32 [%0], {%1,%2,%3,%4};" ::
            "r"(aAddr0), "r"(wx), "r"(wy), "r"(wz), "r"(ww));
        wx = pkh2(av2.x, av2.y); wy = pkh2(av2.z, av2.w);
        wz = pkh2(av3.x, av3.y); ww = pkh2(av3.z, av3.w);
        asm volatile("st.shared.v4.b32 [%0], {%1,%2,%3,%4};" ::
            "r"(aAddr1), "r"(wx), "r"(wy), "r"(wz), "r"(ww));
        wx = pkh2(bv0.x, bv0.y); wy = pkh2(bv0.z, bv0.w);
        wz = pkh2(bv1.x, bv1.y); ww = pkh2(bv1.z, bv1.w);
        asm volatile("st.shared.v4.b32 [%0], {%1,%2,%3,%4};" ::
            "r"(bAddr0), "r"(wx), "r"(wy), "r"(wz), "r"(ww));
        wx = pkh2(bv2.x, bv2.y); wy = pkh2(bv2.z, bv2.w);
        wz = pkh2(bv3.x, bv3.y); ww = pkh2(bv3.z, bv3.w);
        asm volatile("st.shared.v4.b32 [%0], {%1,%2,%3,%4};" ::
            "r"(bAddr1), "r"(wx), "r"(wy), "r"(wz), "r"(ww));

        __syncthreads();

        #pragma unroll
        for (int ks = 0; ks < 2; ks++) {
            // A fragments: 4 m-tiles of 16
            u32 af[4][4];
            #pragma unroll
            for (int mt = 0; mt < 4; mt++) {
                int rr = warp_m * 64 + mt * 16 + ((lane >> 3) & 1) * 8 + (lane & 7);
                int cc = ks * 2 + (lane >> 4);
                u32 aaddr = sA + rr * 64 + (((cc + (rr >> 1)) & 3) << 4);
                asm volatile(
                    "ldmatrix.sync.aligned.m8n8.x4.shared.b16 {%0,%1,%2,%3}, [%4];"
                    : "=r"(af[mt][0]), "=r"(af[mt][1]), "=r"(af[mt][2]), "=r"(af[mt][3])
                    : "r"(aaddr));
            }
            #pragma unroll
            for (int nt = 0; nt < 4; nt++) {
                int rr = ks * 16 + (lane & 15);
                int cc = warp_n * 4 + nt;
                u32 baddr = sB + rr * 256 + ((cc ^ (rr & 7)) << 4);
                u32 bf0, bf1;
                asm volatile(
                    "ldmatrix.sync.aligned.m8n8.x2.trans.shared.b16 {%0,%1}, [%2];"
                    : "=r"(bf0), "=r"(bf1) : "r"(baddr));
                #pragma unroll
                for (int mt = 0; mt < 4; mt++) {
                    asm volatile(
                        "mma.sync.aligned.m16n8k16.row.col.f32.f16.f16.f32 "
                        "{%0,%1,%2,%3}, {%4,%5,%6,%7}, {%8,%9}, {%0,%1,%2,%3};"
                        : "+f"(acc[mt][nt][0]), "+f"(acc[mt][nt][1]),
                          "+f"(acc[mt][nt][2]), "+f"(acc[mt][nt][3])
                        : "r"(af[mt][0]), "r"(af[mt][1]), "r"(af[mt][2]), "r"(af[mt][3]),
                          "r"(bf0), "r"(bf1));
                }
            }
        }
    }

    // epilogue
    const int g = lane >> 2, tl = lane & 3;
    #pragma unroll
    for (int nt = 0; nt < 4; nt++) {
        int col = col0 + warp_n * 32 + nt * 8 + 2 * tl;
        float2 bb = *(const float2*)&bias[col];
        #pragma unroll
        for (int mt = 0; mt < 4; mt++) {
            int rlo = row0 + warp_m * 64 + mt * 16 + g;
            float2 olo, ohi;
            olo.x = acc[mt][nt][0] + bb.x;
            olo.y = acc[mt][nt][1] + bb.y;
            ohi.x = acc[mt][nt][2] + bb.x;
            ohi.y = acc[mt][nt][3] + bb.y;
            if (GELU) {
                olo.x = 0.5f * olo.x * (1.0f + erff(olo.x * 0.70710678118654752f));
                olo.y = 0.5f * olo.y * (1.0f + erff(olo.y * 0.70710678118654752f));
                ohi.x = 0.5f * ohi.x * (1.0f + erff(ohi.x * 0.70710678118654752f));
                ohi.y = 0.5f * ohi.y * (1.0f + erff(ohi.y * 0.70710678118654752f));
            }
            *(float2*)&C[(size_t)rlo * N + col] = olo;
            *(float2*)&C[(size_t)(rlo + 8) * N + col] = ohi;
        }
    }
}

// ---------------------------------------------------------------------------
// Attention. q:[B,Lq=L,D] (head h -> cols h*64..), k/v:[B,Lk,D].
// Block: 256 threads, 16 queries; key tiles of 64 with online softmax.
// WINDOWED: causal local window W=64 + ALiBi bias slope_h*(j-i).
// ---------------------------------------------------------------------------
template<bool WINDOWED>
__global__ __launch_bounds__(256) void attn_kernel(
    const float* __restrict__ q, const float* __restrict__ k,
    const float* __restrict__ v, float* __restrict__ out, int Lk)
{
    __shared__ __align__(16) float q_s[16][64];
    __shared__ float K_s[64 * 65];
    __shared__ __align__(16) float V_s[64 * 64];
    __shared__ float P_s[16 * 64];

    const int tid = threadIdx.x;
    const int b = blockIdx.y >> 4, h = blockIdx.y & 15;
    const int q0 = blockIdx.x * 16;

    const float* qb = q + (size_t)(b * Ll + q0) * Dd + h * DHh;
    const float* kb = k + (size_t)b * Lk * Dd + h * DHh;
    const float* vb = v + (size_t)b * Lk * Dd + h * DHh;

    {
        int ltq = tid >> 4, ld4 = (tid & 15) << 2;
        *(float4*)&q_s[ltq][ld4] = *(const float4*)(qb + (size_t)ltq * Dd + ld4);
    }

    const int tq = tid >> 4, tx = tid & 15;
    const int i = q0 + tq;
    const float slope = WINDOWED ? exp2f(-0.5f * (float)(h + 1)) : 0.0f;

    float m = -3.4e38f, l = 0.0f;
    float o0 = 0.f, o1 = 0.f, o2 = 0.f, o3 = 0.f;

    int t0 = 0, t1 = Lk / 64 - 1;
    if (WINDOWED) {
        int js = q0 - (WINW - 1); if (js < 0) js = 0;
        t0 = js >> 6;
        t1 = (q0 + 15) >> 6;
    }
    __syncthreads();

    for (int t = t0; t <= t1; t++) {
        for (int idx = tid; idx < 4096; idx += 256) {
            int kk = idx >> 6, d = idx & 63;
            K_s[kk * 65 + d] = kb[(size_t)((t << 6) + kk) * Dd + d];
        }
        for (int f = tid; f < 1024; f += 256) {
            int kk = f >> 4, d4 = (f & 15) << 2;
            *(float4*)&V_s[kk * 64 + d4] = *(const float4*)(vb + (size_t)((t << 6) + kk) * Dd + d4);
        }
        __syncthreads();

        float sv[4];
        #pragma unroll
        for (int ii = 0; ii < 4; ii++) {
            int kk = tx + (ii << 4);
            int j = (t << 6) + kk;
            const float* kr = &K_s[kk * 65];
            float s = 0.f;
            #pragma unroll
            for (int d = 0; d < 64; d++) s += q_s[tq][d] * kr[d];
            s *= 0.125f;
            if (WINDOWED) {
                s += slope * (float)(j - i);
                if (j > i || (i - j) >= WINW) s = -3.4e38f;
            }
            sv[ii] = s;
        }

        float mt = fmaxf(fmaxf(sv[0], sv[1]), fmaxf(sv[2], sv[3]));
        #pragma unroll
        for (int off = 8; off >= 1; off >>= 1)
            mt = fmaxf(mt, __shfl_xor_sync(0xffffffffu, mt, off));

        float mnew = fmaxf(m, mt);
        float corr, p0, p1, p2, p3;
        if (mnew < -1e37f) {
            corr = 1.f; p0 = p1 = p2 = p3 = 0.f;
        } else {
            corr = __expf(m - mnew);
            p0 = __expf(sv[0] - mnew);
            p1 = __expf(sv[1] - mnew);
            p2 = __expf(sv[2] - mnew);
            p3 = __expf(sv[3] - mnew);
        }
        float tl = p0 + p1 + p2 + p3;
        #pragma unroll
        for (int off = 8; off >= 1; off >>= 1)
            tl += __shfl_xor_sync(0xffffffffu, tl, off);

        l = l * corr + tl;
        m = mnew;
        o0 *= corr; o1 *= corr; o2 *= corr; o3 *= corr;

        P_s[tq * 64 + tx     ] = p0;
        P_s[tq * 64 + tx + 16] = p1;
        P_s[tq * 64 + tx + 32] = p2;
        P_s[tq * 64 + tx + 48] = p3;
        __syncthreads();

        #pragma unroll
        for (int kk = 0; kk < 64; kk++) {
            float pp = P_s[tq * 64 + kk];
            float4 vv = *(const float4*)&V_s[kk * 64 + (tx << 2)];
            o0 += pp * vv.x; o1 += pp * vv.y; o2 += pp * vv.z; o3 += pp * vv.w;
        }
        __syncthreads();
    }

    float inv = 1.0f / l;
    float4 r;
    r.x = o0 * inv; r.y = o1 * inv; r.z = o2 * inv; r.w = o3 * inv;
    *(float4*)(out + (size_t)(b * Ll + i) * Dd + h * DHh + (tx << 2)) = r;
}

// ---------------------------------------------------------------------------
// out = LayerNorm(a + bres) * g + be, row-wise over D=1024. Block 256 threads.
// ---------------------------------------------------------------------------
__global__ __launch_bounds__(256) void add_ln_kernel(
    const float* __restrict__ a, const float* __restrict__ bres,
    const float* __restrict__ g, const float* __restrict__ be,
    float* __restrict__ out)
{
    const int row = blockIdx.x;
    const int tid = threadIdx.x;
    const int d4 = tid << 2;

    float4 va = *(const float4*)(a + (size_t)row * Dd + d4);
    float4 vb = *(const float4*)(bres + (size_t)row * Dd + d4);
    float x0 = va.x + vb.x, x1 = va.y + vb.y, x2 = va.z + vb.z, x3 = va.w + vb.w;

    float s = x0 + x1 + x2 + x3;
    float ss = x0 * x0 + x1 * x1 + x2 * x2 + x3 * x3;

    #pragma unroll
    for (int off = 16; off >= 1; off >>= 1) {
        s  += __shfl_down_sync(0xffffffffu, s,  off);
        ss += __shfl_down_sync(0xffffffffu, ss, off);
    }
    __shared__ float rs[8], rss[8];
    __shared__ float s_mu, s_rstd;
    if ((tid & 31) == 0) { rs[tid >> 5] = s; rss[tid >> 5] = ss; }
    __syncthreads();
    if (tid == 0) {
        float S = 0.f, SS = 0.f;
        #pragma unroll
        for (int w = 0; w < 8; w++) { S += rs[w]; SS += rss[w]; }
        float mu = S * (1.0f / Dd);
        float var = SS * (1.0f / Dd) - mu * mu;
        s_mu = mu;
        s_rstd = rsqrtf(var + 1e-5f);
    }
    __syncthreads();
    float mu = s_mu, rstd = s_rstd;

    float4 gg = *(const float4*)(g + d4);
    float4 bb = *(const float4*)(be + d4);
    float4 o;
    o.x = (x0 - mu) * rstd * gg.x + bb.x;
    o.y = (x1 - mu) * rstd * gg.y + bb.y;
    o.z = (x2 - mu) * rstd * gg.z + bb.z;
    o.w = (x3 - mu) * rstd * gg.w + bb.w;
    *(float4*)(out + (size_t)row * Dd + d4) = o;
}

// ---------------------------------------------------------------------------
extern "C" void kernel_launch(void* const* d_in, const int* in_sizes, int n_in,
                              void* d_out, int out_size)
{
    const float* x   = (const float*)d_in[0];
    const float* mem = (const float*)d_in[1];

    const float *swq, *sbq, *swk, *sbk, *swv, *sbv, *swo, *sbo;
    const float *cwq, *cbq, *cwk, *cbk, *cwv, *cbv, *cwo, *cbo;
    const float *w1, *b1, *w2, *b2, *g1, *be1, *g2, *be2, *g3, *be3;

    if (in_sizes[3] == Dd) {
        swq=(const float*)d_in[2];  sbq=(const float*)d_in[3];
        swk=(const float*)d_in[4];  sbk=(const float*)d_in[5];
        swv=(const float*)d_in[6];  sbv=(const float*)d_in[7];
        swo=(const float*)d_in[8];  sbo=(const float*)d_in[9];
        cwq=(const float*)d_in[10]; cbq=(const float*)d_in[11];
        cwk=(const float*)d_in[12]; cbk=(const float*)d_in[13];
        cwv=(const float*)d_in[14]; cbv=(const float*)d_in[15];
        cwo=(const float*)d_in[16]; cbo=(const float*)d_in[17];
        w1=(const float*)d_in[18];  b1=(const float*)d_in[19];
        w2=(const float*)d_in[20];  b2=(const float*)d_in[21];
        g1=(const float*)d_in[22];  be1=(const float*)d_in[23];
        g2=(const float*)d_in[24];  be2=(const float*)d_in[25];
        g3=(const float*)d_in[26];  be3=(const float*)d_in[27];
    } else {
        swq=(const float*)d_in[2];  swk=(const float*)d_in[3];
        swv=(const float*)d_in[4];  swo=(const float*)d_in[5];
        sbq=(const float*)d_in[6];  sbk=(const float*)d_in[7];
        sbv=(const float*)d_in[8];  sbo=(const float*)d_in[9];
        cwq=(const float*)d_in[10]; cwk=(const float*)d_in[11];
        cwv=(const float*)d_in[12]; cwo=(const float*)d_in[13];
        cbq=(const float*)d_in[14]; cbk=(const float*)d_in[15];
        cbv=(const float*)d_in[16]; cbo=(const float*)d_in[17];
        w1=(const float*)d_in[18];  b1=(const float*)d_in[19];
        w2=(const float*)d_in[20];  b2=(const float*)d_in[21];
        g1=(const float*)d_in[22];  g2=(const float*)d_in[23];
        g3=(const float*)d_in[24];
        be1=(const float*)d_in[25]; be2=(const float*)d_in[26];
        be3=(const float*)d_in[27];
    }

    float* s = nullptr;
    cudaGetSymbolAddress((void**)&s, g_scratch);
    float* bq   = s;
    float* bk   = s + (size_t)SEG;
    float* bv   = s + (size_t)SEG * 2;
    float* batt = s + (size_t)SEG * 3;
    float* btmp = s + (size_t)SEG * 4;
    float* bx1  = s + (size_t)SEG * 5;
    float* bx2  = s + (size_t)SEG * 6;
    float* bff  = s + (size_t)SEG * 7;

    dim3 gP(Dd / 128, RB / 128);    // projections: N=1024 -> (8,32)
    dim3 gF1(FFf / 128, RB / 128);  // FFN up:      N=4096 -> (32,32)
    dim3 gAttn(Ll / 16, Bb * Hh);

    // ---- self-attention ----
    hgemm_kernel<false><<<gP, 256>>>(x, swq, sbq, bq, Dd, Dd);
    hgemm_kernel<false><<<gP, 256>>>(x, swk, sbk, bk, Dd, Dd);
    hgemm_kernel<false><<<gP, 256>>>(x, swv, sbv, bv, Dd, Dd);
    attn_kernel<true><<<gAttn, 256>>>(bq, bk, bv, batt, Ll);
    hgemm_kernel<false><<<gP, 256>>>(batt, swo, sbo, btmp, Dd, Dd);
    add_ln_kernel<<<RB, 256>>>(x, btmp, g1, be1, bx1);

    // ---- cross-attention ----
    hgemm_kernel<false><<<gP, 256>>>(bx1, cwq, cbq, bq, Dd, Dd);
    hgemm_kernel<false><<<gP, 256>>>(mem, cwk, cbk, bk, Dd, Dd);
    hgemm_kernel<false><<<gP, 256>>>(mem, cwv, cbv, bv, Dd, Dd);
    attn_kernel<false><<<gAttn, 256>>>(bq, bk, bv, batt, Mm);
    hgemm_kernel<false><<<gP, 256>>>(batt, cwo, cbo, btmp, Dd, Dd);
    add_ln_kernel<<<RB, 256>>>(bx1, btmp, g2, be2, bx2);

    // ---- FFN ----
    hgemm_kernel<true><<<gF1, 256>>>(bx2, w1, b1, bff, Dd, FFf);
    hgemm_kernel<false><<<gP, 256>>>(bff, w2, b2, btmp, FFf, Dd);
    add_ln_kernel<<<RB, 256>>>(bx2, btmp, g3, be3, (float*)d_out);
}

// round 4
// speedup vs baseline: 2.9077x; 1.6562x over previous
#include <cuda_runtime.h>
#include <cuda_fp16.h>
#include <cstdint>
#include <math.h>

typedef unsigned int u32;

#define Bb 2
#define Ll 2048
#define Mm 2048
#define Dd 1024
#define Hh 16
#define DHh 64
#define FFf 4096
#define WINW 64
#define RB (Bb*Ll)      // 4096 rows
#define SEG (RB*Dd)     // 4194304

#define M1 (1024*1024)

// fp32 scratch: btmp, bx1, bx2
__device__ float g_f32[(size_t)SEG*3];
// fp16 scratch: 64M halfs (see offsets in kernel_launch)
__device__ __half g_f16[(size_t)64*M1];

#define CP16(dst, src) asm volatile("cp.async.cg.shared.global [%0], [%1], 16;" :: "r"(dst), "l"(src))
#define CPCOMMIT()     asm volatile("cp.async.commit_group;")

// ---------------------------------------------------------------------------
// Batched fp32 -> fp16 conversion (12 tensors in one launch).
// ---------------------------------------------------------------------------
struct CvtJob { const float* src; __half* dst; int n; };
struct CvtArgs { CvtJob job[12]; };

__global__ __launch_bounds__(256) void cvt_kernel(CvtArgs a) {
    CvtJob j = a.job[blockIdx.y];
    int stride = gridDim.x * 256 * 8;
    for (int base = (blockIdx.x * 256 + threadIdx.x) * 8; base < j.n; base += stride) {
        float4 f0 = *(const float4*)(j.src + base);
        float4 f1 = *(const float4*)(j.src + base + 4);
        __half2 h0 = __floats2half2_rn(f0.x, f0.y);
        __half2 h1 = __floats2half2_rn(f0.z, f0.w);
        __half2 h2 = __floats2half2_rn(f1.x, f1.y);
        __half2 h3 = __floats2half2_rn(f1.z, f1.w);
        uint4 o;
        o.x = *(u32*)&h0; o.y = *(u32*)&h1; o.z = *(u32*)&h2; o.w = *(u32*)&h3;
        *(uint4*)(j.dst + base) = o;
    }
}

// ---------------------------------------------------------------------------
// fp16 tensor-core GEMM, cp.async double-buffered.
// C = A[R,K] @ W[K,N] + bias. Optional exact GELU. Writes fp32 and/or fp16.
// Block tile 128x128x32, 8 warps (2x4), warp tile 64x32.
// Smem stage: A 128x32 halfs (rows 64B, chunk swizzle (c+(r>>1))&3),
//             B 32x128 halfs (rows 256B, chunk swizzle c^(r&7)).
// ---------------------------------------------------------------------------
template<bool GELU>
__global__ __launch_bounds__(256, 2) void hgemm16_kernel(
    const __half* __restrict__ A, const __half* __restrict__ Wm,
    const float* __restrict__ bias, float* __restrict__ C32,
    __half* __restrict__ C16, int K, int N)
{
    __shared__ __align__(16) unsigned char smem_buf[2 * 16384];

    const int tid = threadIdx.x;
    const int lane = tid & 31, wid = tid >> 5;
    const int warp_m = wid >> 2, warp_n = wid & 3;
    const int row0 = blockIdx.y * 128, col0 = blockIdx.x * 128;
    const u32 sbase = (u32)__cvta_generic_to_shared(smem_buf);

    float acc[4][4][4];
    #pragma unroll
    for (int i = 0; i < 4; i++)
        #pragma unroll
        for (int j = 0; j < 4; j++)
            #pragma unroll
            for (int q = 0; q < 4; q++) acc[i][j][q] = 0.f;

    const int ar = tid >> 1, akh = tid & 1;   // A: row ar, chunks 2akh,2akh+1
    const int br = tid >> 3, bnh = tid & 7;   // B: row br, chunks 2bnh,2bnh+1

    const __half* Agp = A + (size_t)(row0 + ar) * K + akh * 16;
    const __half* Bgp = Wm + (size_t)br * N + col0 + bnh * 16;

    const u32 aDst0 = sbase + ar * 64 + (((2 * akh    ) + (ar >> 1)) & 3) * 16;
    const u32 aDst1 = sbase + ar * 64 + (((2 * akh + 1) + (ar >> 1)) & 3) * 16;
    const u32 bDst0 = sbase + 8192 + br * 256 + (((2 * bnh    ) ^ (br & 7))) * 16;
    const u32 bDst1 = sbase + 8192 + br * 256 + (((2 * bnh + 1) ^ (br & 7))) * 16;

    const int ntiles = K >> 5;

    // prefetch tile 0 into stage 0
    {
        CP16(aDst0, Agp);
        CP16(aDst1, Agp + 8);
        CP16(bDst0, Bgp);
        CP16(bDst1, Bgp + 8);
        CPCOMMIT();
    }

    for (int t = 0; t < ntiles; t++) {
        if (t + 1 < ntiles) {
            u32 off = ((t + 1) & 1) * 16384;
            int k0 = (t + 1) << 5;
            CP16(aDst0 + off, Agp + k0);
            CP16(aDst1 + off, Agp + k0 + 8);
            CP16(bDst0 + off, Bgp + (size_t)k0 * N);
            CP16(bDst1 + off, Bgp + (size_t)k0 * N + 8);
            CPCOMMIT();
            asm volatile("cp.async.wait_group 1;");
        } else {
            asm volatile("cp.async.wait_group 0;");
        }
        __syncthreads();

        const u32 sA = sbase + (t & 1) * 16384;
        const u32 sB = sA + 8192;

        #pragma unroll
        for (int ks = 0; ks < 2; ks++) {
            u32 af[4][4];
            #pragma unroll
            for (int mt = 0; mt < 4; mt++) {
                int rr = warp_m * 64 + mt * 16 + ((lane >> 3) & 1) * 8 + (lane & 7);
                int cc = ks * 2 + (lane >> 4);
                u32 aaddr = sA + rr * 64 + (((cc + (rr >> 1)) & 3) << 4);
                asm volatile(
                    "ldmatrix.sync.aligned.m8n8.x4.shared.b16 {%0,%1,%2,%3}, [%4];"
                    : "=r"(af[mt][0]), "=r"(af[mt][1]), "=r"(af[mt][2]), "=r"(af[mt][3])
                    : "r"(aaddr));
            }
            #pragma unroll
            for (int nt = 0; nt < 4; nt++) {
                int rr = ks * 16 + (lane & 15);
                int cc = warp_n * 4 + nt;
                u32 baddr = sB + rr * 256 + ((cc ^ (rr & 7)) << 4);
                u32 bf0, bf1;
                asm volatile(
                    "ldmatrix.sync.aligned.m8n8.x2.trans.shared.b16 {%0,%1}, [%2];"
                    : "=r"(bf0), "=r"(bf1) : "r"(baddr));
                #pragma unroll
                for (int mt = 0; mt < 4; mt++) {
                    asm volatile(
                        "mma.sync.aligned.m16n8k16.row.col.f32.f16.f16.f32 "
                        "{%0,%1,%2,%3}, {%4,%5,%6,%7}, {%8,%9}, {%0,%1,%2,%3};"
                        : "+f"(acc[mt][nt][0]), "+f"(acc[mt][nt][1]),
                          "+f"(acc[mt][nt][2]), "+f"(acc[mt][nt][3])
                        : "r"(af[mt][0]), "r"(af[mt][1]), "r"(af[mt][2]), "r"(af[mt][3]),
                          "r"(bf0), "r"(bf1));
                }
            }
        }
        __syncthreads();
    }

    // epilogue
    const int g = lane >> 2, tl = lane & 3;
    #pragma unroll
    for (int nt = 0; nt < 4; nt++) {
        int col = col0 + warp_n * 32 + nt * 8 + 2 * tl;
        float2 bb = *(const float2*)&bias[col];
        #pragma unroll
        for (int mt = 0; mt < 4; mt++) {
            int rlo = row0 + warp_m * 64 + mt * 16 + g;
            float2 olo, ohi;
            olo.x = acc[mt][nt][0] + bb.x;
            olo.y = acc[mt][nt][1] + bb.y;
            ohi.x = acc[mt][nt][2] + bb.x;
            ohi.y = acc[mt][nt][3] + bb.y;
            if (GELU) {
                olo.x = 0.5f * olo.x * (1.0f + erff(olo.x * 0.70710678118654752f));
                olo.y = 0.5f * olo.y * (1.0f + erff(olo.y * 0.70710678118654752f));
                ohi.x = 0.5f * ohi.x * (1.0f + erff(ohi.x * 0.70710678118654752f));
                ohi.y = 0.5f * ohi.y * (1.0f + erff(ohi.y * 0.70710678118654752f));
            }
            if (C32) {
                *(float2*)&C32[(size_t)rlo * N + col] = olo;
                *(float2*)&C32[(size_t)(rlo + 8) * N + col] = ohi;
            }
            if (C16) {
                __half2 hlo = __floats2half2_rn(olo.x, olo.y);
                __half2 hhi = __floats2half2_rn(ohi.x, ohi.y);
                *(__half2*)&C16[(size_t)rlo * N + col] = hlo;
                *(__half2*)&C16[(size_t)(rlo + 8) * N + col] = hhi;
            }
        }
    }
}

// ---------------------------------------------------------------------------
// fp16 attention. q/k/v fp16 [B,L,D]; out fp16. fp32 softmax/accumulate.
// 16 queries/block, key tiles of 64. K_s swizzled 16B chunks; vectorized LDS.
// ---------------------------------------------------------------------------
template<bool WINDOWED>
__global__ __launch_bounds__(256) void attn16_kernel(
    const __half* __restrict__ q, const __half* __restrict__ k,
    const __half* __restrict__ v, __half* __restrict__ out, int Lk)
{
    __shared__ __align__(16) float q_s[16][64];        // 4KB
    __shared__ __align__(16) __half K_s[64 * 64];      // 8KB, chunk swizzle c^(kk&7)
    __shared__ __align__(16) __half V_s[64 * 64];      // 8KB, linear rows 128B
    __shared__ float P_s[16 * 64];                     // 4KB

    const int tid = threadIdx.x;
    const int b = blockIdx.y >> 4, h = blockIdx.y & 15;
    const int q0 = blockIdx.x * 16;

    const __half* qb = q + (size_t)(b * Ll + q0) * Dd + h * DHh;
    const __half* kb = k + (size_t)b * Lk * Dd + h * DHh;
    const __half* vb = v + (size_t)b * Lk * Dd + h * DHh;

    const u32 sK = (u32)__cvta_generic_to_shared(K_s);
    const u32 sV = (u32)__cvta_generic_to_shared(V_s);

    // q fill: 128 threads x 8 halfs, converted to fp32
    if (tid < 128) {
        int r = tid >> 3, c8 = (tid & 7) << 3;
        uint4 raw = *(const uint4*)(qb + (size_t)r * Dd + c8);
        __half2* hp = (__half2*)&raw;
        float2 f0 = __half22float2(hp[0]);
        float2 f1 = __half22float2(hp[1]);
        float2 f2 = __half22float2(hp[2]);
        float2 f3 = __half22float2(hp[3]);
        float4 a; a.x = f0.x; a.y = f0.y; a.z = f1.x; a.w = f1.y;
        float4 bq4; bq4.x = f2.x; bq4.y = f2.y; bq4.z = f3.x; bq4.w = f3.y;
        *(float4*)&q_s[r][c8] = a;
        *(float4*)&q_s[r][c8 + 4] = bq4;
    }

    const int tq = tid >> 4, tx = tid & 15;
    const int i = q0 + tq;
    const float slope = WINDOWED ? exp2f(-0.5f * (float)(h + 1)) : 0.0f;

    float m = -3.4e38f, l = 0.0f;
    float o0 = 0.f, o1 = 0.f, o2 = 0.f, o3 = 0.f;

    int t0 = 0, t1 = Lk / 64 - 1;
    if (WINDOWED) {
        int js = q0 - (WINW - 1); if (js < 0) js = 0;
        t0 = js >> 6;
        t1 = (q0 + 15) >> 6;
    }

    // K/V loader indices: row kk = tid/4, chunks c0,c0+1 (16B each)
    const int lkk = tid >> 2, lc0 = (tid & 3) << 1;
    const u32 kdst0 = sK + lkk * 128 + ((lc0 ^ (lkk & 7)) << 4);
    const u32 kdst1 = sK + lkk * 128 + (((lc0 + 1) ^ (lkk & 7)) << 4);
    const u32 vdst  = sV + lkk * 128 + (lc0 << 4);

    __syncthreads();

    for (int t = t0; t <= t1; t++) {
        {
            const __half* kr = kb + (size_t)((t << 6) + lkk) * Dd + (lc0 << 3);
            const __half* vr = vb + (size_t)((t << 6) + lkk) * Dd + (lc0 << 3);
            CP16(kdst0, kr);
            CP16(kdst1, kr + 8);
            CP16(vdst, vr);
            CP16(vdst + 16, vr + 8);
            CPCOMMIT();
        }
        asm volatile("cp.async.wait_group 0;");
        __syncthreads();

        // scores: 4 keys per thread, vectorized 8-dim chunks
        float sv[4] = {0.f, 0.f, 0.f, 0.f};
        const float* qrow = &q_s[tq][0];
        #pragma unroll
        for (int c = 0; c < 8; c++) {
            float4 qa = *(const float4*)(qrow + (c << 3));
            float4 qb4 = *(const float4*)(qrow + (c << 3) + 4);
            #pragma unroll
            for (int ii = 0; ii < 4; ii++) {
                int kk = tx + (ii << 4);
                const uint4 kvp = *(const uint4*)((const unsigned char*)K_s
                                    + kk * 128 + ((c ^ (kk & 7)) << 4));
                __half2 h0 = *(__half2*)&kvp.x, h1 = *(__half2*)&kvp.y;
                __half2 h2 = *(__half2*)&kvp.z, h3 = *(__half2*)&kvp.w;
                float2 f0 = __half22float2(h0), f1 = __half22float2(h1);
                float2 f2 = __half22float2(h2), f3 = __half22float2(h3);
                sv[ii] += qa.x * f0.x + qa.y * f0.y + qa.z * f1.x + qa.w * f1.y
                        + qb4.x * f2.x + qb4.y * f2.y + qb4.z * f3.x + qb4.w * f3.y;
            }
        }

        #pragma unroll
        for (int ii = 0; ii < 4; ii++) {
            int j = (t << 6) + tx + (ii << 4);
            float s = sv[ii] * 0.125f;
            if (WINDOWED) {
                s += slope * (float)(j - i);
                if (j > i || (i - j) >= WINW) s = -3.4e38f;
            }
            sv[ii] = s;
        }

        float mt = fmaxf(fmaxf(sv[0], sv[1]), fmaxf(sv[2], sv[3]));
        #pragma unroll
        for (int off = 8; off >= 1; off >>= 1)
            mt = fmaxf(mt, __shfl_xor_sync(0xffffffffu, mt, off));

        float mnew = fmaxf(m, mt);
        float corr, p0, p1, p2, p3;
        if (mnew < -1e37f) {
            corr = 1.f; p0 = p1 = p2 = p3 = 0.f;
        } else {
            corr = __expf(m - mnew);
            p0 = __expf(sv[0] - mnew);
            p1 = __expf(sv[1] - mnew);
            p2 = __expf(sv[2] - mnew);
            p3 = __expf(sv[3] - mnew);
        }
        float tl = p0 + p1 + p2 + p3;
        #pragma unroll
        for (int off = 8; off >= 1; off >>= 1)
            tl += __shfl_xor_sync(0xffffffffu, tl, off);

        l = l * corr + tl;
        m = mnew;
        o0 *= corr; o1 *= corr; o2 *= corr; o3 *= corr;

        P_s[tq * 64 + tx     ] = p0;
        P_s[tq * 64 + tx + 16] = p1;
        P_s[tq * 64 + tx + 32] = p2;
        P_s[tq * 64 + tx + 48] = p3;
        __syncthreads();

        #pragma unroll
        for (int kk = 0; kk < 64; kk++) {
            float pp = P_s[tq * 64 + kk];
            uint2 vv = *(const uint2*)((const unsigned char*)V_s + kk * 128 + tx * 8);
            __half2 va = *(__half2*)&vv.x, vbh = *(__half2*)&vv.y;
            float2 fa = __half22float2(va), fb = __half22float2(vbh);
            o0 += pp * fa.x; o1 += pp * fa.y; o2 += pp * fb.x; o3 += pp * fb.y;
        }
        __syncthreads();
    }

    float inv = 1.0f / l;
    __half2 r01 = __floats2half2_rn(o0 * inv, o1 * inv);
    __half2 r23 = __floats2half2_rn(o2 * inv, o3 * inv);
    uint2 ro; ro.x = *(u32*)&r01; ro.y = *(u32*)&r23;
    *(uint2*)(out + (size_t)(b * Ll + i) * Dd + h * DHh + (tx << 2)) = ro;
}

// ---------------------------------------------------------------------------
// out = LayerNorm(a + bres) * g + be. Optional fp16 mirror.
// ---------------------------------------------------------------------------
__global__ __launch_bounds__(256) void add_ln_kernel(
    const float* __restrict__ a, const float* __restrict__ bres,
    const float* __restrict__ g, const float* __restrict__ be,
    float* __restrict__ out, __half* __restrict__ out16)
{
    const int row = blockIdx.x;
    const int tid = threadIdx.x;
    const int d4 = tid << 2;

    float4 va = *(const float4*)(a + (size_t)row * Dd + d4);
    float4 vb = *(const float4*)(bres + (size_t)row * Dd + d4);
    float x0 = va.x + vb.x, x1 = va.y + vb.y, x2 = va.z + vb.z, x3 = va.w + vb.w;

    float s = x0 + x1 + x2 + x3;
    float ss = x0 * x0 + x1 * x1 + x2 * x2 + x3 * x3;

    #pragma unroll
    for (int off = 16; off >= 1; off >>= 1) {
        s  += __shfl_down_sync(0xffffffffu, s,  off);
        ss += __shfl_down_sync(0xffffffffu, ss, off);
    }
    __shared__ float rs[8], rss[8];
    __shared__ float s_mu, s_rstd;
    if ((tid & 31) == 0) { rs[tid >> 5] = s; rss[tid >> 5] = ss; }
    __syncthreads();
    if (tid == 0) {
        float S = 0.f, SS = 0.f;
        #pragma unroll
        for (int w = 0; w < 8; w++) { S += rs[w]; SS += rss[w]; }
        float mu = S * (1.0f / Dd);
        float var = SS * (1.0f / Dd) - mu * mu;
        s_mu = mu;
        s_rstd = rsqrtf(var + 1e-5f);
    }
    __syncthreads();
    float mu = s_mu, rstd = s_rstd;

    float4 gg = *(const float4*)(g + d4);
    float4 bb = *(const float4*)(be + d4);
    float4 o;
    o.x = (x0 - mu) * rstd * gg.x + bb.x;
    o.y = (x1 - mu) * rstd * gg.y + bb.y;
    o.z = (x2 - mu) * rstd * gg.z + bb.z;
    o.w = (x3 - mu) * rstd * gg.w + bb.w;
    *(float4*)(out + (size_t)row * Dd + d4) = o;
    if (out16) {
        __half2 h0 = __floats2half2_rn(o.x, o.y);
        __half2 h1 = __floats2half2_rn(o.z, o.w);
        uint2 ho; ho.x = *(u32*)&h0; ho.y = *(u32*)&h1;
        *(uint2*)(out16 + (size_t)row * Dd + d4) = ho;
    }
}

// ---------------------------------------------------------------------------
extern "C" void kernel_launch(void* const* d_in, const int* in_sizes, int n_in,
                              void* d_out, int out_size)
{
    const float* x   = (const float*)d_in[0];
    const float* mem = (const float*)d_in[1];

    const float *swq, *sbq, *swk, *sbk, *swv, *sbv, *swo, *sbo;
    const float *cwq, *cbq, *cwk, *cbk, *cwv, *cbv, *cwo, *cbo;
    const float *w1, *b1, *w2, *b2, *g1, *be1, *g2, *be2, *g3, *be3;

    if (in_sizes[3] == Dd) {
        swq=(const float*)d_in[2];  sbq=(const float*)d_in[3];
        swk=(const float*)d_in[4];  sbk=(const float*)d_in[5];
        swv=(const float*)d_in[6];  sbv=(const float*)d_in[7];
        swo=(const float*)d_in[8];  sbo=(const float*)d_in[9];
        cwq=(const float*)d_in[10]; cbq=(const float*)d_in[11];
        cwk=(const float*)d_in[12]; cbk=(const float*)d_in[13];
        cwv=(const float*)d_in[14]; cbv=(const float*)d_in[15];
        cwo=(const float*)d_in[16]; cbo=(const float*)d_in[17];
        w1=(const float*)d_in[18];  b1=(const float*)d_in[19];
        w2=(const float*)d_in[20];  b2=(const float*)d_in[21];
        g1=(const float*)d_in[22];  be1=(const float*)d_in[23];
        g2=(const float*)d_in[24];  be2=(const float*)d_in[25];
        g3=(const float*)d_in[26];  be3=(const float*)d_in[27];
    } else {
        swq=(const float*)d_in[2];  swk=(const float*)d_in[3];
        swv=(const float*)d_in[4];  swo=(const float*)d_in[5];
        sbq=(const float*)d_in[6];  sbk=(const float*)d_in[7];
        sbv=(const float*)d_in[8];  sbo=(const float*)d_in[9];
        cwq=(const float*)d_in[10]; cwk=(const float*)d_in[11];
        cwv=(const float*)d_in[12]; cwo=(const float*)d_in[13];
        cbq=(const float*)d_in[14]; cbk=(const float*)d_in[15];
        cbv=(const float*)d_in[16]; cbo=(const float*)d_in[17];
        w1=(const float*)d_in[18];  b1=(const float*)d_in[19];
        w2=(const float*)d_in[20];  b2=(const float*)d_in[21];
        g1=(const float*)d_in[22];  g2=(const float*)d_in[23];
        g3=(const float*)d_in[24];
        be1=(const float*)d_in[25]; be2=(const float*)d_in[26];
        be3=(const float*)d_in[27];
    }

    float* s32 = nullptr;
    cudaGetSymbolAddress((void**)&s32, g_f32);
    __half* s16 = nullptr;
    cudaGetSymbolAddress((void**)&s16, g_f16);

    float* btmp = s32;
    float* bx1  = s32 + (size_t)SEG;
    float* bx2  = s32 + (size_t)SEG * 2;

    __half* x16    = s16;
    __half* mem16  = s16 + (size_t)4*M1;
    __half* wq16   = s16 + (size_t)8*M1;
    __half* wk16   = s16 + (size_t)9*M1;
    __half* wv16   = s16 + (size_t)10*M1;
    __half* wo16   = s16 + (size_t)11*M1;
    __half* cq16   = s16 + (size_t)12*M1;
    __half* ck16   = s16 + (size_t)13*M1;
    __half* cv16   = s16 + (size_t)14*M1;
    __half* co16   = s16 + (size_t)15*M1;
    __half* w1_16  = s16 + (size_t)16*M1;
    __half* w2_16  = s16 + (size_t)20*M1;
    __half* bq16   = s16 + (size_t)24*M1;
    __half* bk16   = s16 + (size_t)28*M1;
    __half* bv16   = s16 + (size_t)32*M1;
    __half* batt16 = s16 + (size_t)36*M1;
    __half* bx1_16 = s16 + (size_t)40*M1;
    __half* bx2_16 = s16 + (size_t)44*M1;
    __half* bff16  = s16 + (size_t)48*M1;

    // convert all fp32 sources to fp16 in one batched launch
    CvtArgs ca;
    ca.job[0]  = { x,   x16,   4*M1 };
    ca.job[1]  = { mem, mem16, 4*M1 };
    ca.job[2]  = { swq, wq16,  M1 };
    ca.job[3]  = { swk, wk16,  M1 };
    ca.job[4]  = { swv, wv16,  M1 };
    ca.job[5]  = { swo, wo16,  M1 };
    ca.job[6]  = { cwq, cq16,  M1 };
    ca.job[7]  = { cwk, ck16,  M1 };
    ca.job[8]  = { cwv, cv16,  M1 };
    ca.job[9]  = { cwo, co16,  M1 };
    ca.job[10] = { w1,  w1_16, 4*M1 };
    ca.job[11] = { w2,  w2_16, 4*M1 };
    dim3 gCvt(512, 12);
    cvt_kernel<<<gCvt, 256>>>(ca);

    dim3 gP(Dd / 128, RB / 128);    // N=1024
    dim3 gF1(FFf / 128, RB / 128);  // N=4096
    dim3 gAttn(Ll / 16, Bb * Hh);

    // ---- self-attention ----
    hgemm16_kernel<false><<<gP, 256>>>(x16, wq16, sbq, nullptr, bq16, Dd, Dd);
    hgemm16_kernel<false><<<gP, 256>>>(x16, wk16, sbk, nullptr, bk16, Dd, Dd);
    hgemm16_kernel<false><<<gP, 256>>>(x16, wv16, sbv, nullptr, bv16, Dd, Dd);
    attn16_kernel<true><<<gAttn, 256>>>(bq16, bk16, bv16, batt16, Ll);
    hgemm16_kernel<false><<<gP, 256>>>(batt16, wo16, sbo, btmp, nullptr, Dd, Dd);
    add_ln_kernel<<<RB, 256>>>(x, btmp, g1, be1, bx1, bx1_16);

    // ---- cross-attention ----
    hgemm16_kernel<false><<<gP, 256>>>(bx1_16, cq16, cbq, nullptr, bq16, Dd, Dd);
    hgemm16_kernel<false><<<gP, 256>>>(mem16, ck16, cbk, nullptr, bk16, Dd, Dd);
    hgemm16_kernel<false><<<gP, 256>>>(mem16, cv16, cbv, nullptr, bv16, Dd, Dd);
    attn16_kernel<false><<<gAttn, 256>>>(bq16, bk16, bv16, batt16, Mm);
    hgemm16_kernel<false><<<gP, 256>>>(batt16, co16, cbo, btmp, nullptr, Dd, Dd);
    add_ln_kernel<<<RB, 256>>>(bx1, btmp, g2, be2, bx2, bx2_16);

    // ---- FFN ----
    hgemm16_kernel<true><<<gF1, 256>>>(bx2_16, w1_16, b1, nullptr, bff16, Dd, FFf);
    hgemm16_kernel<false><<<gP, 256>>>(bff16, w2_16, b2, btmp, nullptr, FFf, Dd);
    add_ln_kernel<<<RB, 256>>>(bx2, btmp, g3, be3, (float*)d_out, nullptr);
}

// round 5
// speedup vs baseline: 8.2388x; 2.8334x over previous
#include <cuda_runtime.h>
#include <cuda_fp16.h>
#include <cstdint>
#include <math.h>

typedef unsigned int u32;

#define Bb 2
#define Ll 2048
#define Mm 2048
#define Dd 1024
#define Hh 16
#define DHh 64
#define FFf 4096
#define WINW 64
#define RB (Bb*Ll)      // 4096 rows
#define SEG (RB*Dd)     // 4194304

#define M1 (1024*1024)

// fp32 scratch: btmp, bx1, bx2
__device__ float g_f32[(size_t)SEG*3];
// fp16 scratch
__device__ __half g_f16[(size_t)64*M1];

#define CP16(dst, src) asm volatile("cp.async.cg.shared.global [%0], [%1], 16;" :: "r"(dst), "l"(src))
#define CPCOMMIT()     asm volatile("cp.async.commit_group;")

// ---------------------------------------------------------------------------
// Batched fp32 -> fp16 conversion (12 tensors in one launch).
// ---------------------------------------------------------------------------
struct CvtJob { const float* src; __half* dst; int n; };
struct CvtArgs { CvtJob job[12]; };

__global__ __launch_bounds__(256) void cvt_kernel(CvtArgs a) {
    CvtJob j = a.job[blockIdx.y];
    int stride = gridDim.x * 256 * 8;
    for (int base = (blockIdx.x * 256 + threadIdx.x) * 8; base < j.n; base += stride) {
        float4 f0 = *(const float4*)(j.src + base);
        float4 f1 = *(const float4*)(j.src + base + 4);
        __half2 h0 = __floats2half2_rn(f0.x, f0.y);
        __half2 h1 = __floats2half2_rn(f0.z, f0.w);
        __half2 h2 = __floats2half2_rn(f1.x, f1.y);
        __half2 h3 = __floats2half2_rn(f1.z, f1.w);
        uint4 o;
        o.x = *(u32*)&h0; o.y = *(u32*)&h1; o.z = *(u32*)&h2; o.w = *(u32*)&h3;
        *(uint4*)(j.dst + base) = o;
    }
}

// ---------------------------------------------------------------------------
// fp16 tensor-core GEMM, cp.async double-buffered (unchanged from R4).
// ---------------------------------------------------------------------------
template<bool GELU>
__global__ __launch_bounds__(256, 2) void hgemm16_kernel(
    const __half* __restrict__ A, const __half* __restrict__ Wm,
    const float* __restrict__ bias, float* __restrict__ C32,
    __half* __restrict__ C16, int K, int N)
{
    __shared__ __align__(16) unsigned char smem_buf[2 * 16384];

    const int tid = threadIdx.x;
    const int lane = tid & 31, wid = tid >> 5;
    const int warp_m = wid >> 2, warp_n = wid & 3;
    const int row0 = blockIdx.y * 128, col0 = blockIdx.x * 128;
    const u32 sbase = (u32)__cvta_generic_to_shared(smem_buf);

    float acc[4][4][4];
    #pragma unroll
    for (int i = 0; i < 4; i++)
        #pragma unroll
        for (int j = 0; j < 4; j++)
            #pragma unroll
            for (int q = 0; q < 4; q++) acc[i][j][q] = 0.f;

    const int ar = tid >> 1, akh = tid & 1;
    const int br = tid >> 3, bnh = tid & 7;

    const __half* Agp = A + (size_t)(row0 + ar) * K + akh * 16;
    const __half* Bgp = Wm + (size_t)br * N + col0 + bnh * 16;

    const u32 aDst0 = sbase + ar * 64 + (((2 * akh    ) + (ar >> 1)) & 3) * 16;
    const u32 aDst1 = sbase + ar * 64 + (((2 * akh + 1) + (ar >> 1)) & 3) * 16;
    const u32 bDst0 = sbase + 8192 + br * 256 + (((2 * bnh    ) ^ (br & 7))) * 16;
    const u32 bDst1 = sbase + 8192 + br * 256 + (((2 * bnh + 1) ^ (br & 7))) * 16;

    const int ntiles = K >> 5;

    {
        CP16(aDst0, Agp);
        CP16(aDst1, Agp + 8);
        CP16(bDst0, Bgp);
        CP16(bDst1, Bgp + 8);
        CPCOMMIT();
    }

    for (int t = 0; t < ntiles; t++) {
        if (t + 1 < ntiles) {
            u32 off = ((t + 1) & 1) * 16384;
            int k0 = (t + 1) << 5;
            CP16(aDst0 + off, Agp + k0);
            CP16(aDst1 + off, Agp + k0 + 8);
            CP16(bDst0 + off, Bgp + (size_t)k0 * N);
            CP16(bDst1 + off, Bgp + (size_t)k0 * N + 8);
            CPCOMMIT();
            asm volatile("cp.async.wait_group 1;");
        } else {
            asm volatile("cp.async.wait_group 0;");
        }
        __syncthreads();

        const u32 sA = sbase + (t & 1) * 16384;
        const u32 sB = sA + 8192;

        #pragma unroll
        for (int ks = 0; ks < 2; ks++) {
            u32 af[4][4];
            #pragma unroll
            for (int mt = 0; mt < 4; mt++) {
                int rr = warp_m * 64 + mt * 16 + ((lane >> 3) & 1) * 8 + (lane & 7);
                int cc = ks * 2 + (lane >> 4);
                u32 aaddr = sA + rr * 64 + (((cc + (rr >> 1)) & 3) << 4);
                asm volatile(
                    "ldmatrix.sync.aligned.m8n8.x4.shared.b16 {%0,%1,%2,%3}, [%4];"
                    : "=r"(af[mt][0]), "=r"(af[mt][1]), "=r"(af[mt][2]), "=r"(af[mt][3])
                    : "r"(aaddr));
            }
            #pragma unroll
            for (int nt = 0; nt < 4; nt++) {
                int rr = ks * 16 + (lane & 15);
                int cc = warp_n * 4 + nt;
                u32 baddr = sB + rr * 256 + ((cc ^ (rr & 7)) << 4);
                u32 bf0, bf1;
                asm volatile(
                    "ldmatrix.sync.aligned.m8n8.x2.trans.shared.b16 {%0,%1}, [%2];"
                    : "=r"(bf0), "=r"(bf1) : "r"(baddr));
                #pragma unroll
                for (int mt = 0; mt < 4; mt++) {
                    asm volatile(
                        "mma.sync.aligned.m16n8k16.row.col.f32.f16.f16.f32 "
                        "{%0,%1,%2,%3}, {%4,%5,%6,%7}, {%8,%9}, {%0,%1,%2,%3};"
                        : "+f"(acc[mt][nt][0]), "+f"(acc[mt][nt][1]),
                          "+f"(acc[mt][nt][2]), "+f"(acc[mt][nt][3])
                        : "r"(af[mt][0]), "r"(af[mt][1]), "r"(af[mt][2]), "r"(af[mt][3]),
                          "r"(bf0), "r"(bf1));
                }
            }
        }
        __syncthreads();
    }

    const int g = lane >> 2, tl = lane & 3;
    #pragma unroll
    for (int nt = 0; nt < 4; nt++) {
        int col = col0 + warp_n * 32 + nt * 8 + 2 * tl;
        float2 bb = *(const float2*)&bias[col];
        #pragma unroll
        for (int mt = 0; mt < 4; mt++) {
            int rlo = row0 + warp_m * 64 + mt * 16 + g;
            float2 olo, ohi;
            olo.x = acc[mt][nt][0] + bb.x;
            olo.y = acc[mt][nt][1] + bb.y;
            ohi.x = acc[mt][nt][2] + bb.x;
            ohi.y = acc[mt][nt][3] + bb.y;
            if (GELU) {
                olo.x = 0.5f * olo.x * (1.0f + erff(olo.x * 0.70710678118654752f));
                olo.y = 0.5f * olo.y * (1.0f + erff(olo.y * 0.70710678118654752f));
                ohi.x = 0.5f * ohi.x * (1.0f + erff(ohi.x * 0.70710678118654752f));
                ohi.y = 0.5f * ohi.y * (1.0f + erff(ohi.y * 0.70710678118654752f));
            }
            if (C32) {
                *(float2*)&C32[(size_t)rlo * N + col] = olo;
                *(float2*)&C32[(size_t)(rlo + 8) * N + col] = ohi;
            }
            if (C16) {
                __half2 hlo = __floats2half2_rn(olo.x, olo.y);
                __half2 hhi = __floats2half2_rn(ohi.x, ohi.y);
                *(__half2*)&C16[(size_t)rlo * N + col] = hlo;
                *(__half2*)&C16[(size_t)(rlo + 8) * N + col] = hhi;
            }
        }
    }
}

// ---------------------------------------------------------------------------
// MMA flash attention. 64-query tile, 4 warps (16 rows each), 64-key tiles.
// Q/K/V fp16, fp32 softmax state, P in fp16. K/V double-buffered cp.async.
// Smem rows: 64 halfs = 128B = 8 chunks of 16B, swizzle chunk c^(row&7).
// ---------------------------------------------------------------------------
template<bool WINDOWED>
__global__ __launch_bounds__(128) void attn_mma_kernel(
    const __half* __restrict__ q, const __half* __restrict__ k,
    const __half* __restrict__ v, __half* __restrict__ out, int Lk)
{
    __shared__ __align__(16) __half Q_s[64 * 64];       // 8KB
    __shared__ __align__(16) __half K_s[2][64 * 64];    // 16KB
    __shared__ __align__(16) __half V_s[2][64 * 64];    // 16KB

    const int tid = threadIdx.x;
    const int lane = tid & 31, wid = tid >> 5;
    const int b = blockIdx.y >> 4, h = blockIdx.y & 15;
    const int q0 = blockIdx.x * 64;

    const __half* qb = q + (size_t)(b * Ll + q0) * Dd + h * DHh;
    const __half* kb = k + (size_t)b * Lk * Dd + h * DHh;
    const __half* vb = v + (size_t)b * Lk * Dd + h * DHh;

    const u32 sQ  = (u32)__cvta_generic_to_shared(Q_s);
    const u32 sK0 = (u32)__cvta_generic_to_shared(K_s);
    const u32 sV0 = (u32)__cvta_generic_to_shared(V_s);

    const float slope = WINDOWED ? exp2f(-0.5f * (float)(h + 1)) : 0.0f;

    int t0 = 0, t1 = Lk / 64 - 1;
    if (WINDOWED) { t0 = (q0 >> 6) - 1; if (t0 < 0) t0 = 0; t1 = q0 >> 6; }

    // loader: row lr = tid/2, chunks lc0..lc0+3
    const int lr = tid >> 1, lc0 = (tid & 1) * 4;

    // Q tile
    #pragma unroll
    for (int c = 0; c < 4; c++) {
        int cc = lc0 + c;
        CP16(sQ + lr * 128 + ((cc ^ (lr & 7)) << 4), qb + (size_t)lr * Dd + cc * 8);
    }
    CPCOMMIT();
    // K/V tile t0 -> buffer 0
    {
        const __half* kr = kb + (size_t)(t0 * 64 + lr) * Dd;
        const __half* vr = vb + (size_t)(t0 * 64 + lr) * Dd;
        #pragma unroll
        for (int c = 0; c < 4; c++) {
            int cc = lc0 + c;
            u32 doff = lr * 128 + ((cc ^ (lr & 7)) << 4);
            CP16(sK0 + doff, kr + cc * 8);
            CP16(sV0 + doff, vr + cc * 8);
        }
        CPCOMMIT();
    }
    asm volatile("cp.async.wait_group 0;");
    __syncthreads();

    // Q fragments (persist across tiles)
    u32 qf[4][4];
    #pragma unroll
    for (int ks = 0; ks < 4; ks++) {
        int rr = wid * 16 + ((lane >> 3) & 1) * 8 + (lane & 7);
        int cc = ks * 2 + (lane >> 4);
        u32 addr = sQ + rr * 128 + ((cc ^ (rr & 7)) << 4);
        asm volatile(
            "ldmatrix.sync.aligned.m8n8.x4.shared.b16 {%0,%1,%2,%3}, [%4];"
            : "=r"(qf[ks][0]), "=r"(qf[ks][1]), "=r"(qf[ks][2]), "=r"(qf[ks][3])
            : "r"(addr));
    }

    float m0 = -3.4e38f, m1 = -3.4e38f, l0 = 0.f, l1 = 0.f;
    float oacc[8][4];
    #pragma unroll
    for (int nt = 0; nt < 8; nt++)
        #pragma unroll
        for (int e = 0; e < 4; e++) oacc[nt][e] = 0.f;

    const int qr = lane >> 2;          // local row 0..7 (and +8)
    const int qc2 = (lane & 3) << 1;   // col pair base within n-tile

    for (int t = t0; t <= t1; t++) {
        int buf = (t - t0) & 1;
        if (t < t1) {
            u32 off = (buf ^ 1) * 8192;
            const __half* kr = kb + (size_t)((t + 1) * 64 + lr) * Dd;
            const __half* vr = vb + (size_t)((t + 1) * 64 + lr) * Dd;
            #pragma unroll
            for (int c = 0; c < 4; c++) {
                int cc = lc0 + c;
                u32 doff = lr * 128 + ((cc ^ (lr & 7)) << 4);
                CP16(sK0 + off + doff, kr + cc * 8);
                CP16(sV0 + off + doff, vr + cc * 8);
            }
            CPCOMMIT();
            asm volatile("cp.async.wait_group 1;");
        } else {
            asm volatile("cp.async.wait_group 0;");
        }
        __syncthreads();

        const u32 sK = sK0 + buf * 8192;
        const u32 sV = sV0 + buf * 8192;

        // ---- S = Q @ K^T ----
        float sacc[8][4];
        #pragma unroll
        for (int nt = 0; nt < 8; nt++) {
            sacc[nt][0] = sacc[nt][1] = sacc[nt][2] = sacc[nt][3] = 0.f;
            #pragma unroll
            for (int ks = 0; ks < 4; ks++) {
                int krow = nt * 8 + (lane & 7);
                int cc = ks * 2 + ((lane >> 3) & 1);
                u32 addr = sK + krow * 128 + ((cc ^ (krow & 7)) << 4);
                u32 bf0, bf1;
                asm volatile(
                    "ldmatrix.sync.aligned.m8n8.x2.shared.b16 {%0,%1}, [%2];"
                    : "=r"(bf0), "=r"(bf1) : "r"(addr));
                asm volatile(
                    "mma.sync.aligned.m16n8k16.row.col.f32.f16.f16.f32 "
                    "{%0,%1,%2,%3}, {%4,%5,%6,%7}, {%8,%9}, {%0,%1,%2,%3};"
                    : "+f"(sacc[nt][0]), "+f"(sacc[nt][1]),
                      "+f"(sacc[nt][2]), "+f"(sacc[nt][3])
                    : "r"(qf[ks][0]), "r"(qf[ks][1]), "r"(qf[ks][2]), "r"(qf[ks][3]),
                      "r"(bf0), "r"(bf1));
            }
        }

        // ---- softmax (rows r0 = qr, r1 = qr+8 of this warp's 16) ----
        float mt0 = -3.4e38f, mt1 = -3.4e38f;
        #pragma unroll
        for (int nt = 0; nt < 8; nt++) {
            #pragma unroll
            for (int e = 0; e < 4; e++) {
                float s = sacc[nt][e] * 0.125f;
                if (WINDOWED) {
                    int i = q0 + wid * 16 + qr + ((e >> 1) << 3);
                    int j = t * 64 + nt * 8 + qc2 + (e & 1);
                    s += slope * (float)(j - i);
                    if (j > i || (i - j) >= WINW) s = -3.4e38f;
                }
                sacc[nt][e] = s;
                if (e < 2) mt0 = fmaxf(mt0, s); else mt1 = fmaxf(mt1, s);
            }
        }
        mt0 = fmaxf(mt0, __shfl_xor_sync(0xffffffffu, mt0, 1));
        mt0 = fmaxf(mt0, __shfl_xor_sync(0xffffffffu, mt0, 2));
        mt1 = fmaxf(mt1, __shfl_xor_sync(0xffffffffu, mt1, 1));
        mt1 = fmaxf(mt1, __shfl_xor_sync(0xffffffffu, mt1, 2));

        float mn0 = fmaxf(m0, mt0), mn1 = fmaxf(m1, mt1);
        bool dead0 = mn0 < -1e37f, dead1 = mn1 < -1e37f;
        float corr0 = dead0 ? 1.f : __expf(m0 - mn0);
        float corr1 = dead1 ? 1.f : __expf(m1 - mn1);

        float ls0 = 0.f, ls1 = 0.f;
        #pragma unroll
        for (int nt = 0; nt < 8; nt++) {
            float p0 = dead0 ? 0.f : __expf(sacc[nt][0] - mn0);
            float p1 = dead0 ? 0.f : __expf(sacc[nt][1] - mn0);
            float p2 = dead1 ? 0.f : __expf(sacc[nt][2] - mn1);
            float p3 = dead1 ? 0.f : __expf(sacc[nt][3] - mn1);
            sacc[nt][0] = p0; sacc[nt][1] = p1; sacc[nt][2] = p2; sacc[nt][3] = p3;
            ls0 += p0 + p1; ls1 += p2 + p3;
        }
        ls0 += __shfl_xor_sync(0xffffffffu, ls0, 1);
        ls0 += __shfl_xor_sync(0xffffffffu, ls0, 2);
        ls1 += __shfl_xor_sync(0xffffffffu, ls1, 1);
        ls1 += __shfl_xor_sync(0xffffffffu, ls1, 2);

        l0 = l0 * corr0 + ls0;
        l1 = l1 * corr1 + ls1;
        m0 = mn0; m1 = mn1;

        #pragma unroll
        for (int nt = 0; nt < 8; nt++) {
            oacc[nt][0] *= corr0; oacc[nt][1] *= corr0;
            oacc[nt][2] *= corr1; oacc[nt][3] *= corr1;
        }

        // ---- O += P @ V ----
        #pragma unroll
        for (int ks = 0; ks < 4; ks++) {
            __half2 ph0 = __floats2half2_rn(sacc[2*ks][0], sacc[2*ks][1]);
            __half2 ph1 = __floats2half2_rn(sacc[2*ks][2], sacc[2*ks][3]);
            __half2 ph2 = __floats2half2_rn(sacc[2*ks+1][0], sacc[2*ks+1][1]);
            __half2 ph3 = __floats2half2_rn(sacc[2*ks+1][2], sacc[2*ks+1][3]);
            u32 pa0 = *(u32*)&ph0, pa1 = *(u32*)&ph1;
            u32 pa2 = *(u32*)&ph2, pa3 = *(u32*)&ph3;
            #pragma unroll
            for (int nt = 0; nt < 8; nt++) {
                int vrow = ks * 16 + (lane & 15);
                u32 addr = sV + vrow * 128 + ((nt ^ (vrow & 7)) << 4);
                u32 vf0, vf1;
                asm volatile(
                    "ldmatrix.sync.aligned.m8n8.x2.trans.shared.b16 {%0,%1}, [%2];"
                    : "=r"(vf0), "=r"(vf1) : "r"(addr));
                asm volatile(
                    "mma.sync.aligned.m16n8k16.row.col.f32.f16.f16.f32 "
                    "{%0,%1,%2,%3}, {%4,%5,%6,%7}, {%8,%9}, {%0,%1,%2,%3};"
                    : "+f"(oacc[nt][0]), "+f"(oacc[nt][1]),
                      "+f"(oacc[nt][2]), "+f"(oacc[nt][3])
                    : "r"(pa0), "r"(pa1), "r"(pa2), "r"(pa3),
                      "r"(vf0), "r"(vf1));
            }
        }
        __syncthreads();
    }

    // ---- write out (fp16) ----
    float inv0 = 1.0f / l0, inv1 = 1.0f / l1;
    int row_lo = q0 + wid * 16 + qr;
    __half* ob = out + (size_t)(b * Ll) * Dd + h * DHh;
    #pragma unroll
    for (int nt = 0; nt < 8; nt++) {
        __half2 h0 = __floats2half2_rn(oacc[nt][0] * inv0, oacc[nt][1] * inv0);
        __half2 h1 = __floats2half2_rn(oacc[nt][2] * inv1, oacc[nt][3] * inv1);
        *(__half2*)(ob + (size_t)row_lo * Dd + nt * 8 + qc2) = h0;
        *(__half2*)(ob + (size_t)(row_lo + 8) * Dd + nt * 8 + qc2) = h1;
    }
}

// ---------------------------------------------------------------------------
// out = LayerNorm(a + bres) * g + be. Optional fp16 mirror.
// ---------------------------------------------------------------------------
__global__ __launch_bounds__(256) void add_ln_kernel(
    const float* __restrict__ a, const float* __restrict__ bres,
    const float* __restrict__ g, const float* __restrict__ be,
    float* __restrict__ out, __half* __restrict__ out16)
{
    const int row = blockIdx.x;
    const int tid = threadIdx.x;
    const int d4 = tid << 2;

    float4 va = *(const float4*)(a + (size_t)row * Dd + d4);
    float4 vb = *(const float4*)(bres + (size_t)row * Dd + d4);
    float x0 = va.x + vb.x, x1 = va.y + vb.y, x2 = va.z + vb.z, x3 = va.w + vb.w;

    float s = x0 + x1 + x2 + x3;
    float ss = x0 * x0 + x1 * x1 + x2 * x2 + x3 * x3;

    #pragma unroll
    for (int off = 16; off >= 1; off >>= 1) {
        s  += __shfl_down_sync(0xffffffffu, s,  off);
        ss += __shfl_down_sync(0xffffffffu, ss, off);
    }
    __shared__ float rs[8], rss[8];
    __shared__ float s_mu, s_rstd;
    if ((tid & 31) == 0) { rs[tid >> 5] = s; rss[tid >> 5] = ss; }
    __syncthreads();
    if (tid == 0) {
        float S = 0.f, SS = 0.f;
        #pragma unroll
        for (int w = 0; w < 8; w++) { S += rs[w]; SS += rss[w]; }
        float mu = S * (1.0f / Dd);
        float var = SS * (1.0f / Dd) - mu * mu;
        s_mu = mu;
        s_rstd = rsqrtf(var + 1e-5f);
    }
    __syncthreads();
    float mu = s_mu, rstd = s_rstd;

    float4 gg = *(const float4*)(g + d4);
    float4 bb = *(const float4*)(be + d4);
    float4 o;
    o.x = (x0 - mu) * rstd * gg.x + bb.x;
    o.y = (x1 - mu) * rstd * gg.y + bb.y;
    o.z = (x2 - mu) * rstd * gg.z + bb.z;
    o.w = (x3 - mu) * rstd * gg.w + bb.w;
    *(float4*)(out + (size_t)row * Dd + d4) = o;
    if (out16) {
        __half2 h0 = __floats2half2_rn(o.x, o.y);
        __half2 h1 = __floats2half2_rn(o.z, o.w);
        uint2 ho; ho.x = *(u32*)&h0; ho.y = *(u32*)&h1;
        *(uint2*)(out16 + (size_t)row * Dd + d4) = ho;
    }
}

// ---------------------------------------------------------------------------
extern "C" void kernel_launch(void* const* d_in, const int* in_sizes, int n_in,
                              void* d_out, int out_size)
{
    const float* x   = (const float*)d_in[0];
    const float* mem = (const float*)d_in[1];

    const float *swq, *sbq, *swk, *sbk, *swv, *sbv, *swo, *sbo;
    const float *cwq, *cbq, *cwk, *cbk, *cwv, *cbv, *cwo, *cbo;
    const float *w1, *b1, *w2, *b2, *g1, *be1, *g2, *be2, *g3, *be3;

    if (in_sizes[3] == Dd) {
        swq=(const float*)d_in[2];  sbq=(const float*)d_in[3];
        swk=(const float*)d_in[4];  sbk=(const float*)d_in[5];
        swv=(const float*)d_in[6];  sbv=(const float*)d_in[7];
        swo=(const float*)d_in[8];  sbo=(const float*)d_in[9];
        cwq=(const float*)d_in[10]; cbq=(const float*)d_in[11];
        cwk=(const float*)d_in[12]; cbk=(const float*)d_in[13];
        cwv=(const float*)d_in[14]; cbv=(const float*)d_in[15];
        cwo=(const float*)d_in[16]; cbo=(const float*)d_in[17];
        w1=(const float*)d_in[18];  b1=(const float*)d_in[19];
        w2=(const float*)d_in[20];  b2=(const float*)d_in[21];
        g1=(const float*)d_in[22];  be1=(const float*)d_in[23];
        g2=(const float*)d_in[24];  be2=(const float*)d_in[25];
        g3=(const float*)d_in[26];  be3=(const float*)d_in[27];
    } else {
        swq=(const float*)d_in[2];  swk=(const float*)d_in[3];
        swv=(const float*)d_in[4];  swo=(const float*)d_in[5];
        sbq=(const float*)d_in[6];  sbk=(const float*)d_in[7];
        sbv=(const float*)d_in[8];  sbo=(const float*)d_in[9];
        cwq=(const float*)d_in[10]; cwk=(const float*)d_in[11];
        cwv=(const float*)d_in[12]; cwo=(const float*)d_in[13];
        cbq=(const float*)d_in[14]; cbk=(const float*)d_in[15];
        cbv=(const float*)d_in[16]; cbo=(const float*)d_in[17];
        w1=(const float*)d_in[18];  b1=(const float*)d_in[19];
        w2=(const float*)d_in[20];  b2=(const float*)d_in[21];
        g1=(const float*)d_in[22];  g2=(const float*)d_in[23];
        g3=(const float*)d_in[24];
        be1=(const float*)d_in[25]; be2=(const float*)d_in[26];
        be3=(const float*)d_in[27];
    }

    float* s32 = nullptr;
    cudaGetSymbolAddress((void**)&s32, g_f32);
    __half* s16 = nullptr;
    cudaGetSymbolAddress((void**)&s16, g_f16);

    float* btmp = s32;
    float* bx1  = s32 + (size_t)SEG;
    float* bx2  = s32 + (size_t)SEG * 2;

    __half* x16    = s16;
    __half* mem16  = s16 + (size_t)4*M1;
    __half* wq16   = s16 + (size_t)8*M1;
    __half* wk16   = s16 + (size_t)9*M1;
    __half* wv16   = s16 + (size_t)10*M1;
    __half* wo16   = s16 + (size_t)11*M1;
    __half* cq16   = s16 + (size_t)12*M1;
    __half* ck16   = s16 + (size_t)13*M1;
    __half* cv16   = s16 + (size_t)14*M1;
    __half* co16   = s16 + (size_t)15*M1;
    __half* w1_16  = s16 + (size_t)16*M1;
    __half* w2_16  = s16 + (size_t)20*M1;
    __half* bq16   = s16 + (size_t)24*M1;
    __half* bk16   = s16 + (size_t)28*M1;
    __half* bv16   = s16 + (size_t)32*M1;
    __half* batt16 = s16 + (size_t)36*M1;
    __half* bx1_16 = s16 + (size_t)40*M1;
    __half* bx2_16 = s16 + (size_t)44*M1;
    __half* bff16  = s16 + (size_t)48*M1;

    CvtArgs ca;
    ca.job[0]  = { x,   x16,   4*M1 };
    ca.job[1]  = { mem, mem16, 4*M1 };
    ca.job[2]  = { swq, wq16,  M1 };
    ca.job[3]  = { swk, wk16,  M1 };
    ca.job[4]  = { swv, wv16,  M1 };
    ca.job[5]  = { swo, wo16,  M1 };
    ca.job[6]  = { cwq, cq16,  M1 };
    ca.job[7]  = { cwk, ck16,  M1 };
    ca.job[8]  = { cwv, cv16,  M1 };
    ca.job[9]  = { cwo, co16,  M1 };
    ca.job[10] = { w1,  w1_16, 4*M1 };
    ca.job[11] = { w2,  w2_16, 4*M1 };
    dim3 gCvt(512, 12);
    cvt_kernel<<<gCvt, 256>>>(ca);

    dim3 gP(Dd / 128, RB / 128);
    dim3 gF1(FFf / 128, RB / 128);
    dim3 gAttn(Ll / 64, Bb * Hh);

    // ---- self-attention ----
    hgemm16_kernel<false><<<gP, 256>>>(x16, wq16, sbq, nullptr, bq16, Dd, Dd);
    hgemm16_kernel<false><<<gP, 256>>>(x16, wk16, sbk, nullptr, bk16, Dd, Dd);
    hgemm16_kernel<false><<<gP, 256>>>(x16, wv16, sbv, nullptr, bv16, Dd, Dd);
    attn_mma_kernel<true><<<gAttn, 128>>>(bq16, bk16, bv16, batt16, Ll);
    hgemm16_kernel<false><<<gP, 256>>>(batt16, wo16, sbo, btmp, nullptr, Dd, Dd);
    add_ln_kernel<<<RB, 256>>>(x, btmp, g1, be1, bx1, bx1_16);

    // ---- cross-attention ----
    hgemm16_kernel<false><<<gP, 256>>>(bx1_16, cq16, cbq, nullptr, bq16, Dd, Dd);
    hgemm16_kernel<false><<<gP, 256>>>(mem16, ck16, cbk, nullptr, bk16, Dd, Dd);
    hgemm16_kernel<false><<<gP, 256>>>(mem16, cv16, cbv, nullptr, bv16, Dd, Dd);
    attn_mma_kernel<false><<<gAttn, 128>>>(bq16, bk16, bv16, batt16, Mm);
    hgemm16_kernel<false><<<gP, 256>>>(batt16, co16, cbo, btmp, nullptr, Dd, Dd);
    add_ln_kernel<<<RB, 256>>>(bx1, btmp, g2, be2, bx2, bx2_16);

    // ---- FFN ----
    hgemm16_kernel<true><<<gF1, 256>>>(bx2_16, w1_16, b1, nullptr, bff16, Dd, FFf);
    hgemm16_kernel<false><<<gP, 256>>>(bff16, w2_16, b2, btmp, nullptr, FFf, Dd);
    add_ln_kernel<<<RB, 256>>>(bx2, btmp, g3, be3, (float*)d_out, nullptr);
}

// round 7
// speedup vs baseline: 8.3500x; 1.0135x over previous
#include <cuda_runtime.h>
#include <cuda_fp16.h>
#include <cstdint>
#include <math.h>

typedef unsigned int u32;

#define Bb 2
#define Ll 2048
#define Mm 2048
#define Dd 1024
#define Hh 16
#define DHh 64
#define FFf 4096
#define WINW 64
#define RB (Bb*Ll)      // 4096 rows
#define SEG (RB*Dd)     // 4194304

#define M1 (1024*1024)

// fp32 scratch: btmp, bx1, bx2
__device__ float g_f32[(size_t)SEG*3];
// fp16 scratch
__device__ __half g_f16[(size_t)64*M1];

#define CP16(dst, src) asm volatile("cp.async.cg.shared.global [%0], [%1], 16;" :: "r"(dst), "l"(src))
#define CPCOMMIT()     asm volatile("cp.async.commit_group;")

// ---------------------------------------------------------------------------
// Batched fp32 -> fp16 conversion (12 tensors in one launch).
// ---------------------------------------------------------------------------
struct CvtJob { const float* src; __half* dst; int n; };
struct CvtArgs { CvtJob job[12]; };

__global__ __launch_bounds__(256) void cvt_kernel(CvtArgs a) {
    CvtJob j = a.job[blockIdx.y];
    int stride = gridDim.x * 256 * 8;
    for (int base = (blockIdx.x * 256 + threadIdx.x) * 8; base < j.n; base += stride) {
        float4 f0 = *(const float4*)(j.src + base);
        float4 f1 = *(const float4*)(j.src + base + 4);
        __half2 h0 = __floats2half2_rn(f0.x, f0.y);
        __half2 h1 = __floats2half2_rn(f0.z, f0.w);
        __half2 h2 = __floats2half2_rn(f1.x, f1.y);
        __half2 h3 = __floats2half2_rn(f1.z, f1.w);
        uint4 o;
        o.x = *(u32*)&h0; o.y = *(u32*)&h1; o.z = *(u32*)&h2; o.w = *(u32*)&h3;
        *(uint4*)(j.dst + base) = o;
    }
}

// ---------------------------------------------------------------------------
// fp16 tensor-core GEMM. 3-stage cp.async pipeline, one barrier/iteration.
// Block tile 128x128x32, 8 warps (2x4), warp tile 64x32.
// ---------------------------------------------------------------------------
template<bool GELU>
__global__ __launch_bounds__(256, 2) void hgemm16_kernel(
    const __half* __restrict__ A, const __half* __restrict__ Wm,
    const float* __restrict__ bias, float* __restrict__ C32,
    __half* __restrict__ C16, int K, int N)
{
    __shared__ __align__(16) unsigned char smem_buf[3 * 16384];   // 48KB

    const int tid = threadIdx.x;
    const int lane = tid & 31, wid = tid >> 5;
    const int warp_m = wid >> 2, warp_n = wid & 3;
    const int row0 = blockIdx.y * 128, col0 = blockIdx.x * 128;
    const u32 sbase = (u32)__cvta_generic_to_shared(smem_buf);

    float acc[4][4][4];
    #pragma unroll
    for (int i = 0; i < 4; i++)
        #pragma unroll
        for (int j = 0; j < 4; j++)
            #pragma unroll
            for (int q = 0; q < 4; q++) acc[i][j][q] = 0.f;

    const int ar = tid >> 1, akh = tid & 1;
    const int br = tid >> 3, bnh = tid & 7;

    const __half* Agp = A + (size_t)(row0 + ar) * K + akh * 16;
    const __half* Bgp = Wm + (size_t)br * N + col0 + bnh * 16;

    const u32 aDst0 = sbase + ar * 64 + (((2 * akh    ) + (ar >> 1)) & 3) * 16;
    const u32 aDst1 = sbase + ar * 64 + (((2 * akh + 1) + (ar >> 1)) & 3) * 16;
    const u32 bDst0 = sbase + 8192 + br * 256 + (((2 * bnh    ) ^ (br & 7))) * 16;
    const u32 bDst1 = sbase + 8192 + br * 256 + (((2 * bnh + 1) ^ (br & 7))) * 16;

    const int ntiles = K >> 5;

    // prefetch tiles 0 and 1 into stages 0 and 1
    #pragma unroll
    for (int p = 0; p < 2; p++) {
        u32 off = p * 16384;
        int k0 = p << 5;
        CP16(aDst0 + off, Agp + k0);
        CP16(aDst1 + off, Agp + k0 + 8);
        CP16(bDst0 + off, Bgp + (size_t)k0 * N);
        CP16(bDst1 + off, Bgp + (size_t)k0 * N + 8);
        CPCOMMIT();
    }

    int stage = 0, pstage = 2;   // stage read this iter, stage to prefetch into
    for (int t = 0; t < ntiles; t++) {
        // retire through group t (one newer group stays in flight)
        asm volatile("cp.async.wait_group 1;");
        __syncthreads();

        // prefetch t+2 (always commit, even if empty — keeps group counting uniform)
        if (t + 2 < ntiles) {
            u32 off = pstage * 16384;
            int k0 = (t + 2) << 5;
            CP16(aDst0 + off, Agp + k0);
            CP16(aDst1 + off, Agp + k0 + 8);
            CP16(bDst0 + off, Bgp + (size_t)k0 * N);
            CP16(bDst1 + off, Bgp + (size_t)k0 * N + 8);
        }
        CPCOMMIT();

        const u32 sA = sbase + stage * 16384;
        const u32 sB = sA + 8192;

        #pragma unroll
        for (int ks = 0; ks < 2; ks++) {
            u32 af[4][4];
            #pragma unroll
            for (int mt = 0; mt < 4; mt++) {
                int rr = warp_m * 64 + mt * 16 + ((lane >> 3) & 1) * 8 + (lane & 7);
                int cc = ks * 2 + (lane >> 4);
                u32 aaddr = sA + rr * 64 + (((cc + (rr >> 1)) & 3) << 4);
                asm volatile(
                    "ldmatrix.sync.aligned.m8n8.x4.shared.b16 {%0,%1,%2,%3}, [%4];"
                    : "=r"(af[mt][0]), "=r"(af[mt][1]), "=r"(af[mt][2]), "=r"(af[mt][3])
                    : "r"(aaddr));
            }
            #pragma unroll
            for (int nt = 0; nt < 4; nt++) {
                int rr = ks * 16 + (lane & 15);
                int cc = warp_n * 4 + nt;
                u32 baddr = sB + rr * 256 + ((cc ^ (rr & 7)) << 4);
                u32 bf0, bf1;
                asm volatile(
                    "ldmatrix.sync.aligned.m8n8.x2.trans.shared.b16 {%0,%1}, [%2];"
                    : "=r"(bf0), "=r"(bf1) : "r"(baddr));
                #pragma unroll
                for (int mt = 0; mt < 4; mt++) {
                    asm volatile(
                        "mma.sync.aligned.m16n8k16.row.col.f32.f16.f16.f32 "
                        "{%0,%1,%2,%3}, {%4,%5,%6,%7}, {%8,%9}, {%0,%1,%2,%3};"
                        : "+f"(acc[mt][nt][0]), "+f"(acc[mt][nt][1]),
                          "+f"(acc[mt][nt][2]), "+f"(acc[mt][nt][3])
                        : "r"(af[mt][0]), "r"(af[mt][1]), "r"(af[mt][2]), "r"(af[mt][3]),
                          "r"(bf0), "r"(bf1));
                }
            }
        }

        stage = (stage == 2) ? 0 : stage + 1;
        pstage = (pstage == 2) ? 0 : pstage + 1;
    }

    const int g = lane >> 2, tl = lane & 3;
    #pragma unroll
    for (int nt = 0; nt < 4; nt++) {
        int col = col0 + warp_n * 32 + nt * 8 + 2 * tl;
        float2 bb = *(const float2*)&bias[col];
        #pragma unroll
        for (int mt = 0; mt < 4; mt++) {
            int rlo = row0 + warp_m * 64 + mt * 16 + g;
            float2 olo, ohi;
            olo.x = acc[mt][nt][0] + bb.x;
            olo.y = acc[mt][nt][1] + bb.y;
            ohi.x = acc[mt][nt][2] + bb.x;
            ohi.y = acc[mt][nt][3] + bb.y;
            if (GELU) {
                olo.x = 0.5f * olo.x * (1.0f + erff(olo.x * 0.70710678118654752f));
                olo.y = 0.5f * olo.y * (1.0f + erff(olo.y * 0.70710678118654752f));
                ohi.x = 0.5f * ohi.x * (1.0f + erff(ohi.x * 0.70710678118654752f));
                ohi.y = 0.5f * ohi.y * (1.0f + erff(ohi.y * 0.70710678118654752f));
            }
            if (C32) {
                *(float2*)&C32[(size_t)rlo * N + col] = olo;
                *(float2*)&C32[(size_t)(rlo + 8) * N + col] = ohi;
            }
            if (C16) {
                __half2 hlo = __floats2half2_rn(olo.x, olo.y);
                __half2 hhi = __floats2half2_rn(ohi.x, ohi.y);
                *(__half2*)&C16[(size_t)rlo * N + col] = hlo;
                *(__half2*)&C16[(size_t)(rlo + 8) * N + col] = hhi;
            }
        }
    }
}

// ---------------------------------------------------------------------------
// MMA flash attention (unchanged from R5).
// ---------------------------------------------------------------------------
template<bool WINDOWED>
__global__ __launch_bounds__(128) void attn_mma_kernel(
    const __half* __restrict__ q, const __half* __restrict__ k,
    const __half* __restrict__ v, __half* __restrict__ out, int Lk)
{
    __shared__ __align__(16) __half Q_s[64 * 64];
    __shared__ __align__(16) __half K_s[2][64 * 64];
    __shared__ __align__(16) __half V_s[2][64 * 64];

    const int tid = threadIdx.x;
    const int lane = tid & 31, wid = tid >> 5;
    const int b = blockIdx.y >> 4, h = blockIdx.y & 15;
    const int q0 = blockIdx.x * 64;

    const __half* qb = q + (size_t)(b * Ll + q0) * Dd + h * DHh;
    const __half* kb = k + (size_t)b * Lk * Dd + h * DHh;
    const __half* vb = v + (size_t)b * Lk * Dd + h * DHh;

    const u32 sQ  = (u32)__cvta_generic_to_shared(Q_s);
    const u32 sK0 = (u32)__cvta_generic_to_shared(K_s);
    const u32 sV0 = (u32)__cvta_generic_to_shared(V_s);

    const float slope = WINDOWED ? exp2f(-0.5f * (float)(h + 1)) : 0.0f;

    int t0 = 0, t1 = Lk / 64 - 1;
    if (WINDOWED) { t0 = (q0 >> 6) - 1; if (t0 < 0) t0 = 0; t1 = q0 >> 6; }

    const int lr = tid >> 1, lc0 = (tid & 1) * 4;

    #pragma unroll
    for (int c = 0; c < 4; c++) {
        int cc = lc0 + c;
        CP16(sQ + lr * 128 + ((cc ^ (lr & 7)) << 4), qb + (size_t)lr * Dd + cc * 8);
    }
    CPCOMMIT();
    {
        const __half* kr = kb + (size_t)(t0 * 64 + lr) * Dd;
        const __half* vr = vb + (size_t)(t0 * 64 + lr) * Dd;
        #pragma unroll
        for (int c = 0; c < 4; c++) {
            int cc = lc0 + c;
            u32 doff = lr * 128 + ((cc ^ (lr & 7)) << 4);
            CP16(sK0 + doff, kr + cc * 8);
            CP16(sV0 + doff, vr + cc * 8);
        }
        CPCOMMIT();
    }
    asm volatile("cp.async.wait_group 0;");
    __syncthreads();

    u32 qf[4][4];
    #pragma unroll
    for (int ks = 0; ks < 4; ks++) {
        int rr = wid * 16 + ((lane >> 3) & 1) * 8 + (lane & 7);
        int cc = ks * 2 + (lane >> 4);
        u32 addr = sQ + rr * 128 + ((cc ^ (rr & 7)) << 4);
        asm volatile(
            "ldmatrix.sync.aligned.m8n8.x4.shared.b16 {%0,%1,%2,%3}, [%4];"
            : "=r"(qf[ks][0]), "=r"(qf[ks][1]), "=r"(qf[ks][2]), "=r"(qf[ks][3])
            : "r"(addr));
    }

    float m0 = -3.4e38f, m1 = -3.4e38f, l0 = 0.f, l1 = 0.f;
    float oacc[8][4];
    #pragma unroll
    for (int nt = 0; nt < 8; nt++)
        #pragma unroll
        for (int e = 0; e < 4; e++) oacc[nt][e] = 0.f;

    const int qr = lane >> 2;
    const int qc2 = (lane & 3) << 1;

    for (int t = t0; t <= t1; t++) {
        int buf = (t - t0) & 1;
        if (t < t1) {
            u32 off = (buf ^ 1) * 8192;
            const __half* kr = kb + (size_t)((t + 1) * 64 + lr) * Dd;
            const __half* vr = vb + (size_t)((t + 1) * 64 + lr) * Dd;
            #pragma unroll
            for (int c = 0; c < 4; c++) {
                int cc = lc0 + c;
                u32 doff = lr * 128 + ((cc ^ (lr & 7)) << 4);
                CP16(sK0 + off + doff, kr + cc * 8);
                CP16(sV0 + off + doff, vr + cc * 8);
            }
            CPCOMMIT();
            asm volatile("cp.async.wait_group 1;");
        } else {
            asm volatile("cp.async.wait_group 0;");
        }
        __syncthreads();

        const u32 sK = sK0 + buf * 8192;
        const u32 sV = sV0 + buf * 8192;

        float sacc[8][4];
        #pragma unroll
        for (int nt = 0; nt < 8; nt++) {
            sacc[nt][0] = sacc[nt][1] = sacc[nt][2] = sacc[nt][3] = 0.f;
            #pragma unroll
            for (int ks = 0; ks < 4; ks++) {
                int krow = nt * 8 + (lane & 7);
                int cc = ks * 2 + ((lane >> 3) & 1);
                u32 addr = sK + krow * 128 + ((cc ^ (krow & 7)) << 4);
                u32 bf0, bf1;
                asm volatile(
                    "ldmatrix.sync.aligned.m8n8.x2.shared.b16 {%0,%1}, [%2];"
                    : "=r"(bf0), "=r"(bf1) : "r"(addr));
                asm volatile(
                    "mma.sync.aligned.m16n8k16.row.col.f32.f16.f16.f32 "
                    "{%0,%1,%2,%3}, {%4,%5,%6,%7}, {%8,%9}, {%0,%1,%2,%3};"
                    : "+f"(sacc[nt][0]), "+f"(sacc[nt][1]),
                      "+f"(sacc[nt][2]), "+f"(sacc[nt][3])
                    : "r"(qf[ks][0]), "r"(qf[ks][1]), "r"(qf[ks][2]), "r"(qf[ks][3]),
                      "r"(bf0), "r"(bf1));
            }
        }

        float mt0 = -3.4e38f, mt1 = -3.4e38f;
        #pragma unroll
        for (int nt = 0; nt < 8; nt++) {
            #pragma unroll
            for (int e = 0; e < 4; e++) {
                float s = sacc[nt][e] * 0.125f;
                if (WINDOWED) {
                    int i = q0 + wid * 16 + qr + ((e >> 1) << 3);
                    int j = t * 64 + nt * 8 + qc2 + (e & 1);
                    s += slope * (float)(j - i);
                    if (j > i || (i - j) >= WINW) s = -3.4e38f;
                }
                sacc[nt][e] = s;
                if (e < 2) mt0 = fmaxf(mt0, s); else mt1 = fmaxf(mt1, s);
            }
        }
        mt0 = fmaxf(mt0, __shfl_xor_sync(0xffffffffu, mt0, 1));
        mt0 = fmaxf(mt0, __shfl_xor_sync(0xffffffffu, mt0, 2));
        mt1 = fmaxf(mt1, __shfl_xor_sync(0xffffffffu, mt1, 1));
        mt1 = fmaxf(mt1, __shfl_xor_sync(0xffffffffu, mt1, 2));

        float mn0 = fmaxf(m0, mt0), mn1 = fmaxf(m1, mt1);
        bool dead0 = mn0 < -1e37f, dead1 = mn1 < -1e37f;
        float corr0 = dead0 ? 1.f : __expf(m0 - mn0);
        float corr1 = dead1 ? 1.f : __expf(m1 - mn1);

        float ls0 = 0.f, ls1 = 0.f;
        #pragma unroll
        for (int nt = 0; nt < 8; nt++) {
            float p0 = dead0 ? 0.f : __expf(sacc[nt][0] - mn0);
            float p1 = dead0 ? 0.f : __expf(sacc[nt][1] - mn0);
            float p2 = dead1 ? 0.f : __expf(sacc[nt][2] - mn1);
            float p3 = dead1 ? 0.f : __expf(sacc[nt][3] - mn1);
            sacc[nt][0] = p0; sacc[nt][1] = p1; sacc[nt][2] = p2; sacc[nt][3] = p3;
            ls0 += p0 + p1; ls1 += p2 + p3;
        }
        ls0 += __shfl_xor_sync(0xffffffffu, ls0, 1);
        ls0 += __shfl_xor_sync(0xffffffffu, ls0, 2);
        ls1 += __shfl_xor_sync(0xffffffffu, ls1, 1);
        ls1 += __shfl_xor_sync(0xffffffffu, ls1, 2);

        l0 = l0 * corr0 + ls0;
        l1 = l1 * corr1 + ls1;
        m0 = mn0; m1 = mn1;

        #pragma unroll
        for (int nt = 0; nt < 8; nt++) {
            oacc[nt][0] *= corr0; oacc[nt][1] *= corr0;
            oacc[nt][2] *= corr1; oacc[nt][3] *= corr1;
        }

        #pragma unroll
        for (int ks = 0; ks < 4; ks++) {
            __half2 ph0 = __floats2half2_rn(sacc[2*ks][0], sacc[2*ks][1]);
            __half2 ph1 = __floats2half2_rn(sacc[2*ks][2], sacc[2*ks][3]);
            __half2 ph2 = __floats2half2_rn(sacc[2*ks+1][0], sacc[2*ks+1][1]);
            __half2 ph3 = __floats2half2_rn(sacc[2*ks+1][2], sacc[2*ks+1][3]);
            u32 pa0 = *(u32*)&ph0, pa1 = *(u32*)&ph1;
            u32 pa2 = *(u32*)&ph2, pa3 = *(u32*)&ph3;
            #pragma unroll
            for (int nt = 0; nt < 8; nt++) {
                int vrow = ks * 16 + (lane & 15);
                u32 addr = sV + vrow * 128 + ((nt ^ (vrow & 7)) << 4);
                u32 vf0, vf1;
                asm volatile(
                    "ldmatrix.sync.aligned.m8n8.x2.trans.shared.b16 {%0,%1}, [%2];"
                    : "=r"(vf0), "=r"(vf1) : "r"(addr));
                asm volatile(
                    "mma.sync.aligned.m16n8k16.row.col.f32.f16.f16.f32 "
                    "{%0,%1,%2,%3}, {%4,%5,%6,%7}, {%8,%9}, {%0,%1,%2,%3};"
                    : "+f"(oacc[nt][0]), "+f"(oacc[nt][1]),
                      "+f"(oacc[nt][2]), "+f"(oacc[nt][3])
                    : "r"(pa0), "r"(pa1), "r"(pa2), "r"(pa3),
                      "r"(vf0), "r"(vf1));
            }
        }
        __syncthreads();
    }

    float inv0 = 1.0f / l0, inv1 = 1.0f / l1;
    int row_lo = q0 + wid * 16 + qr;
    __half* ob = out + (size_t)(b * Ll) * Dd + h * DHh;
    #pragma unroll
    for (int nt = 0; nt < 8; nt++) {
        __half2 h0 = __floats2half2_rn(oacc[nt][0] * inv0, oacc[nt][1] * inv0);
        __half2 h1 = __floats2half2_rn(oacc[nt][2] * inv1, oacc[nt][3] * inv1);
        *(__half2*)(ob + (size_t)row_lo * Dd + nt * 8 + qc2) = h0;
        *(__half2*)(ob + (size_t)(row_lo + 8) * Dd + nt * 8 + qc2) = h1;
    }
}

// ---------------------------------------------------------------------------
// out = LayerNorm(a + bres) * g + be. Optional fp16 mirror.
// ---------------------------------------------------------------------------
__global__ __launch_bounds__(256) void add_ln_kernel(
    const float* __restrict__ a, const float* __restrict__ bres,
    const float* __restrict__ g, const float* __restrict__ be,
    float* __restrict__ out, __half* __restrict__ out16)
{
    const int row = blockIdx.x;
    const int tid = threadIdx.x;
    const int d4 = tid << 2;

    float4 va = *(const float4*)(a + (size_t)row * Dd + d4);
    float4 vb = *(const float4*)(bres + (size_t)row * Dd + d4);
    float x0 = va.x + vb.x, x1 = va.y + vb.y, x2 = va.z + vb.z, x3 = va.w + vb.w;

    float s = x0 + x1 + x2 + x3;
    float ss = x0 * x0 + x1 * x1 + x2 * x2 + x3 * x3;

    #pragma unroll
    for (int off = 16; off >= 1; off >>= 1) {
        s  += __shfl_down_sync(0xffffffffu, s,  off);
        ss += __shfl_down_sync(0xffffffffu, ss, off);
    }
    __shared__ float rs[8], rss[8];
    __shared__ float s_mu, s_rstd;
    if ((tid & 31) == 0) { rs[tid >> 5] = s; rss[tid >> 5] = ss; }
    __syncthreads();
    if (tid == 0) {
        float S = 0.f, SS = 0.f;
        #pragma unroll
        for (int w = 0; w < 8; w++) { S += rs[w]; SS += rss[w]; }
        float mu = S * (1.0f / Dd);
        float var = SS * (1.0f / Dd) - mu * mu;
        s_mu = mu;
        s_rstd = rsqrtf(var + 1e-5f);
    }
    __syncthreads();
    float mu = s_mu, rstd = s_rstd;

    float4 gg = *(const float4*)(g + d4);
    float4 bb = *(const float4*)(be + d4);
    float4 o;
    o.x = (x0 - mu) * rstd * gg.x + bb.x;
    o.y = (x1 - mu) * rstd * gg.y + bb.y;
    o.z = (x2 - mu) * rstd * gg.z + bb.z;
    o.w = (x3 - mu) * rstd * gg.w + bb.w;
    *(float4*)(out + (size_t)row * Dd + d4) = o;
    if (out16) {
        __half2 h0 = __floats2half2_rn(o.x, o.y);
        __half2 h1 = __floats2half2_rn(o.z, o.w);
        uint2 ho; ho.x = *(u32*)&h0; ho.y = *(u32*)&h1;
        *(uint2*)(out16 + (size_t)row * Dd + d4) = ho;
    }
}

// ---------------------------------------------------------------------------
extern "C" void kernel_launch(void* const* d_in, const int* in_sizes, int n_in,
                              void* d_out, int out_size)
{
    const float* x   = (const float*)d_in[0];
    const float* mem = (const float*)d_in[1];

    const float *swq, *sbq, *swk, *sbk, *swv, *sbv, *swo, *sbo;
    const float *cwq, *cbq, *cwk, *cbk, *cwv, *cbv, *cwo, *cbo;
    const float *w1, *b1, *w2, *b2, *g1, *be1, *g2, *be2, *g3, *be3;

    if (in_sizes[3] == Dd) {
        swq=(const float*)d_in[2];  sbq=(const float*)d_in[3];
        swk=(const float*)d_in[4];  sbk=(const float*)d_in[5];
        swv=(const float*)d_in[6];  sbv=(const float*)d_in[7];
        swo=(const float*)d_in[8];  sbo=(const float*)d_in[9];
        cwq=(const float*)d_in[10]; cbq=(const float*)d_in[11];
        cwk=(const float*)d_in[12]; cbk=(const float*)d_in[13];
        cwv=(const float*)d_in[14]; cbv=(const float*)d_in[15];
        cwo=(const float*)d_in[16]; cbo=(const float*)d_in[17];
        w1=(const float*)d_in[18];  b1=(const float*)d_in[19];
        w2=(const float*)d_in[20];  b2=(const float*)d_in[21];
        g1=(const float*)d_in[22];  be1=(const float*)d_in[23];
        g2=(const float*)d_in[24];  be2=(const float*)d_in[25];
        g3=(const float*)d_in[26];  be3=(const float*)d_in[27];
    } else {
        swq=(const float*)d_in[2];  swk=(const float*)d_in[3];
        swv=(const float*)d_in[4];  swo=(const float*)d_in[5];
        sbq=(const float*)d_in[6];  sbk=(const float*)d_in[7];
        sbv=(const float*)d_in[8];  sbo=(const float*)d_in[9];
        cwq=(const float*)d_in[10]; cwk=(const float*)d_in[11];
        cwv=(const float*)d_in[12]; cwo=(const float*)d_in[13];
        cbq=(const float*)d_in[14]; cbk=(const float*)d_in[15];
        cbv=(const float*)d_in[16]; cbo=(const float*)d_in[17];
        w1=(const float*)d_in[18];  b1=(const float*)d_in[19];
        w2=(const float*)d_in[20];  b2=(const float*)d_in[21];
        g1=(const float*)d_in[22];  g2=(const float*)d_in[23];
        g3=(const float*)d_in[24];
        be1=(const float*)d_in[25]; be2=(const float*)d_in[26];
        be3=(const float*)d_in[27];
    }

    float* s32 = nullptr;
    cudaGetSymbolAddress((void**)&s32, g_f32);
    __half* s16 = nullptr;
    cudaGetSymbolAddress((void**)&s16, g_f16);

    float* btmp = s32;
    float* bx1  = s32 + (size_t)SEG;
    float* bx2  = s32 + (size_t)SEG * 2;

    __half* x16    = s16;
    __half* mem16  = s16 + (size_t)4*M1;
    __half* wq16   = s16 + (size_t)8*M1;
    __half* wk16   = s16 + (size_t)9*M1;
    __half* wv16   = s16 + (size_t)10*M1;
    __half* wo16   = s16 + (size_t)11*M1;
    __half* cq16   = s16 + (size_t)12*M1;
    __half* ck16   = s16 + (size_t)13*M1;
    __half* cv16   = s16 + (size_t)14*M1;
    __half* co16   = s16 + (size_t)15*M1;
    __half* w1_16  = s16 + (size_t)16*M1;
    __half* w2_16  = s16 + (size_t)20*M1;
    __half* bq16   = s16 + (size_t)24*M1;
    __half* bk16   = s16 + (size_t)28*M1;
    __half* bv16   = s16 + (size_t)32*M1;
    __half* batt16 = s16 + (size_t)36*M1;
    __half* bx1_16 = s16 + (size_t)40*M1;
    __half* bx2_16 = s16 + (size_t)44*M1;
    __half* bff16  = s16 + (size_t)48*M1;

    CvtArgs ca;
    ca.job[0]  = { x,   x16,   4*M1 };
    ca.job[1]  = { mem, mem16, 4*M1 };
    ca.job[2]  = { swq, wq16,  M1 };
    ca.job[3]  = { swk, wk16,  M1 };
    ca.job[4]  = { swv, wv16,  M1 };
    ca.job[5]  = { swo, wo16,  M1 };
    ca.job[6]  = { cwq, cq16,  M1 };
    ca.job[7]  = { cwk, ck16,  M1 };
    ca.job[8]  = { cwv, cv16,  M1 };
    ca.job[9]  = { cwo, co16,  M1 };
    ca.job[10] = { w1,  w1_16, 4*M1 };
    ca.job[11] = { w2,  w2_16, 4*M1 };
    dim3 gCvt(512, 12);
    cvt_kernel<<<gCvt, 256>>>(ca);

    dim3 gP(Dd / 128, RB / 128);
    dim3 gF1(FFf / 128, RB / 128);
    dim3 gAttn(Ll / 64, Bb * Hh);

    // ---- self-attention ----
    hgemm16_kernel<false><<<gP, 256>>>(x16, wq16, sbq, nullptr, bq16, Dd, Dd);
    hgemm16_kernel<false><<<gP, 256>>>(x16, wk16, sbk, nullptr, bk16, Dd, Dd);
    hgemm16_kernel<false><<<gP, 256>>>(x16, wv16, sbv, nullptr, bv16, Dd, Dd);
    attn_mma_kernel<true><<<gAttn, 128>>>(bq16, bk16, bv16, batt16, Ll);
    hgemm16_kernel<false><<<gP, 256>>>(batt16, wo16, sbo, btmp, nullptr, Dd, Dd);
    add_ln_kernel<<<RB, 256>>>(x, btmp, g1, be1, bx1, bx1_16);

    // ---- cross-attention ----
    hgemm16_kernel<false><<<gP, 256>>>(bx1_16, cq16, cbq, nullptr, bq16, Dd, Dd);
    hgemm16_kernel<false><<<gP, 256>>>(mem16, ck16, cbk, nullptr, bk16, Dd, Dd);
    hgemm16_kernel<false><<<gP, 256>>>(mem16, cv16, cbv, nullptr, bv16, Dd, Dd);
    attn_mma_kernel<false><<<gAttn, 128>>>(bq16, bk16, bv16, batt16, Mm);
    hgemm16_kernel<false><<<gP, 256>>>(batt16, co16, cbo, btmp, nullptr, Dd, Dd);
    add_ln_kernel<<<RB, 256>>>(bx1, btmp, g2, be2, bx2, bx2_16);

    // ---- FFN ----
    hgemm16_kernel<true><<<gF1, 256>>>(bx2_16, w1_16, b1, nullptr, bff16, Dd, FFf);
    hgemm16_kernel<false><<<gP, 256>>>(bff16, w2_16, b2, btmp, nullptr, FFf, Dd);
    add_ln_kernel<<<RB, 256>>>(bx2, btmp, g3, be3, (float*)d_out, nullptr);
}

// round 10
// speedup vs baseline: 8.3940x; 1.0053x over previous
#include <cuda_runtime.h>
#include <cuda_fp16.h>
#include <cstdint>
#include <math.h>

typedef unsigned int u32;

#define Bb 2
#define Ll 2048
#define Mm 2048
#define Dd 1024
#define Hh 16
#define DHh 64
#define FFf 4096
#define WINW 64
#define RB (Bb*Ll)      // 4096 rows
#define SEG (RB*Dd)     // 4194304

#define M1 (1024*1024)

// fp32 scratch: btmp, bx1, bx2
__device__ float g_f32[(size_t)SEG*3];
// fp16 scratch
__device__ __half g_f16[(size_t)64*M1];

#define CP16(dst, src) asm volatile("cp.async.cg.shared.global [%0], [%1], 16;" :: "r"(dst), "l"(src))
#define CPCOMMIT()     asm volatile("cp.async.commit_group;")

// ---------------------------------------------------------------------------
// Batched fp32 -> fp16 conversion (12 tensors in one launch).
// ---------------------------------------------------------------------------
struct CvtJob { const float* src; __half* dst; int n; };
struct CvtArgs { CvtJob job[12]; };

__global__ __launch_bounds__(256) void cvt_kernel(CvtArgs a) {
    CvtJob j = a.job[blockIdx.y];
    int stride = gridDim.x * 256 * 8;
    for (int base = (blockIdx.x * 256 + threadIdx.x) * 8; base < j.n; base += stride) {
        float4 f0 = *(const float4*)(j.src + base);
        float4 f1 = *(const float4*)(j.src + base + 4);
        __half2 h0 = __floats2half2_rn(f0.x, f0.y);
        __half2 h1 = __floats2half2_rn(f0.z, f0.w);
        __half2 h2 = __floats2half2_rn(f1.x, f1.y);
        __half2 h3 = __floats2half2_rn(f1.z, f1.w);
        uint4 o;
        o.x = *(u32*)&h0; o.y = *(u32*)&h1; o.z = *(u32*)&h2; o.w = *(u32*)&h3;
        *(uint4*)(j.dst + base) = o;
    }
}

// ---------------------------------------------------------------------------
// fp16 tensor-core GEMM. 3-stage cp.async pipeline.
// Inner loop: full operand prefetch (4x ldmatrix A + 4x ldmatrix B) then a
// 16-HMMA burst -> one scoreboard stall per ks instead of four.
// Block tile 128x128x32, 8 warps (2x4), warp tile 64x32.
// ---------------------------------------------------------------------------
template<bool GELU>
__global__ __launch_bounds__(256, 2) void hgemm16_kernel(
    const __half* __restrict__ A, const __half* __restrict__ Wm,
    const float* __restrict__ bias, float* __restrict__ C32,
    __half* __restrict__ C16, int K, int N)
{
    __shared__ __align__(16) unsigned char smem_buf[3 * 16384];   // 48KB

    const int tid = threadIdx.x;
    const int lane = tid & 31, wid = tid >> 5;
    const int warp_m = wid >> 2, warp_n = wid & 3;
    const int row0 = blockIdx.y * 128, col0 = blockIdx.x * 128;
    const u32 sbase = (u32)__cvta_generic_to_shared(smem_buf);

    float acc[4][4][4];
    #pragma unroll
    for (int i = 0; i < 4; i++)
        #pragma unroll
        for (int j = 0; j < 4; j++)
            #pragma unroll
            for (int q = 0; q < 4; q++) acc[i][j][q] = 0.f;

    const int ar = tid >> 1, akh = tid & 1;
    const int br = tid >> 3, bnh = tid & 7;

    const __half* Agp = A + (size_t)(row0 + ar) * K + akh * 16;
    const __half* Bgp = Wm + (size_t)br * N + col0 + bnh * 16;

    const u32 aDst0 = sbase + ar * 64 + (((2 * akh    ) + (ar >> 1)) & 3) * 16;
    const u32 aDst1 = sbase + ar * 64 + (((2 * akh + 1) + (ar >> 1)) & 3) * 16;
    const u32 bDst0 = sbase + 8192 + br * 256 + (((2 * bnh    ) ^ (br & 7))) * 16;
    const u32 bDst1 = sbase + 8192 + br * 256 + (((2 * bnh + 1) ^ (br & 7))) * 16;

    const int ntiles = K >> 5;

    // prefetch tiles 0 and 1 into stages 0 and 1
    #pragma unroll
    for (int p = 0; p < 2; p++) {
        u32 off = p * 16384;
        int k0 = p << 5;
        CP16(aDst0 + off, Agp + k0);
        CP16(aDst1 + off, Agp + k0 + 8);
        CP16(bDst0 + off, Bgp + (size_t)k0 * N);
        CP16(bDst1 + off, Bgp + (size_t)k0 * N + 8);
        CPCOMMIT();
    }

    int stage = 0, pstage = 2;
    for (int t = 0; t < ntiles; t++) {
        asm volatile("cp.async.wait_group 1;");
        __syncthreads();

        if (t + 2 < ntiles) {
            u32 off = pstage * 16384;
            int k0 = (t + 2) << 5;
            CP16(aDst0 + off, Agp + k0);
            CP16(aDst1 + off, Agp + k0 + 8);
            CP16(bDst0 + off, Bgp + (size_t)k0 * N);
            CP16(bDst1 + off, Bgp + (size_t)k0 * N + 8);
        }
        CPCOMMIT();

        const u32 sA = sbase + stage * 16384;
        const u32 sB = sA + 8192;

        #pragma unroll
        for (int ks = 0; ks < 2; ks++) {
            // ---- operand prefetch: all A frags, then all B frags ----
            u32 af[4][4];
            #pragma unroll
            for (int mt = 0; mt < 4; mt++) {
                int rr = warp_m * 64 + mt * 16 + ((lane >> 3) & 1) * 8 + (lane & 7);
                int cc = ks * 2 + (lane >> 4);
                u32 aaddr = sA + rr * 64 + (((cc + (rr >> 1)) & 3) << 4);
                asm volatile(
                    "ldmatrix.sync.aligned.m8n8.x4.shared.b16 {%0,%1,%2,%3}, [%4];"
                    : "=r"(af[mt][0]), "=r"(af[mt][1]), "=r"(af[mt][2]), "=r"(af[mt][3])
                    : "r"(aaddr));
            }
            u32 bf[4][2];
            #pragma unroll
            for (int nt = 0; nt < 4; nt++) {
                int rr = ks * 16 + (lane & 15);
                int cc = warp_n * 4 + nt;
                u32 baddr = sB + rr * 256 + ((cc ^ (rr & 7)) << 4);
                asm volatile(
                    "ldmatrix.sync.aligned.m8n8.x2.trans.shared.b16 {%0,%1}, [%2];"
                    : "=r"(bf[nt][0]), "=r"(bf[nt][1]) : "r"(baddr));
            }
            // ---- 16-HMMA burst on landed operands ----
            #pragma unroll
            for (int nt = 0; nt < 4; nt++) {
                #pragma unroll
                for (int mt = 0; mt < 4; mt++) {
                    asm volatile(
                        "mma.sync.aligned.m16n8k16.row.col.f32.f16.f16.f32 "
                        "{%0,%1,%2,%3}, {%4,%5,%6,%7}, {%8,%9}, {%0,%1,%2,%3};"
                        : "+f"(acc[mt][nt][0]), "+f"(acc[mt][nt][1]),
                          "+f"(acc[mt][nt][2]), "+f"(acc[mt][nt][3])
                        : "r"(af[mt][0]), "r"(af[mt][1]), "r"(af[mt][2]), "r"(af[mt][3]),
                          "r"(bf[nt][0]), "r"(bf[nt][1]));
                }
            }
        }

        stage = (stage == 2) ? 0 : stage + 1;
        pstage = (pstage == 2) ? 0 : pstage + 1;
    }

    const int g = lane >> 2, tl = lane & 3;
    #pragma unroll
    for (int nt = 0; nt < 4; nt++) {
        int col = col0 + warp_n * 32 + nt * 8 + 2 * tl;
        float2 bb = *(const float2*)&bias[col];
        #pragma unroll
        for (int mt = 0; mt < 4; mt++) {
            int rlo = row0 + warp_m * 64 + mt * 16 + g;
            float2 olo, ohi;
            olo.x = acc[mt][nt][0] + bb.x;
            olo.y = acc[mt][nt][1] + bb.y;
            ohi.x = acc[mt][nt][2] + bb.x;
            ohi.y = acc[mt][nt][3] + bb.y;
            if (GELU) {
                olo.x = 0.5f * olo.x * (1.0f + erff(olo.x * 0.70710678118654752f));
                olo.y = 0.5f * olo.y * (1.0f + erff(olo.y * 0.70710678118654752f));
                ohi.x = 0.5f * ohi.x * (1.0f + erff(ohi.x * 0.70710678118654752f));
                ohi.y = 0.5f * ohi.y * (1.0f + erff(ohi.y * 0.70710678118654752f));
            }
            if (C32) {
                *(float2*)&C32[(size_t)rlo * N + col] = olo;
                *(float2*)&C32[(size_t)(rlo + 8) * N + col] = ohi;
            }
            if (C16) {
                __half2 hlo = __floats2half2_rn(olo.x, olo.y);
                __half2 hhi = __floats2half2_rn(ohi.x, ohi.y);
                *(__half2*)&C16[(size_t)rlo * N + col] = hlo;
                *(__half2*)&C16[(size_t)(rlo + 8) * N + col] = hhi;
            }
        }
    }
}

// ---------------------------------------------------------------------------
// MMA flash attention (unchanged — passing since R5).
// ---------------------------------------------------------------------------
template<bool WINDOWED>
__global__ __launch_bounds__(128) void attn_mma_kernel(
    const __half* __restrict__ q, const __half* __restrict__ k,
    const __half* __restrict__ v, __half* __restrict__ out, int Lk)
{
    __shared__ __align__(16) __half Q_s[64 * 64];
    __shared__ __align__(16) __half K_s[2][64 * 64];
    __shared__ __align__(16) __half V_s[2][64 * 64];

    const int tid = threadIdx.x;
    const int lane = tid & 31, wid = tid >> 5;
    const int b = blockIdx.y >> 4, h = blockIdx.y & 15;
    const int q0 = blockIdx.x * 64;

    const __half* qb = q + (size_t)(b * Ll + q0) * Dd + h * DHh;
    const __half* kb = k + (size_t)b * Lk * Dd + h * DHh;
    const __half* vb = v + (size_t)b * Lk * Dd + h * DHh;

    const u32 sQ  = (u32)__cvta_generic_to_shared(Q_s);
    const u32 sK0 = (u32)__cvta_generic_to_shared(K_s);
    const u32 sV0 = (u32)__cvta_generic_to_shared(V_s);

    const float slope = WINDOWED ? exp2f(-0.5f * (float)(h + 1)) : 0.0f;

    int t0 = 0, t1 = Lk / 64 - 1;
    if (WINDOWED) { t0 = (q0 >> 6) - 1; if (t0 < 0) t0 = 0; t1 = q0 >> 6; }

    const int lr = tid >> 1, lc0 = (tid & 1) * 4;

    #pragma unroll
    for (int c = 0; c < 4; c++) {
        int cc = lc0 + c;
        CP16(sQ + lr * 128 + ((cc ^ (lr & 7)) << 4), qb + (size_t)lr * Dd + cc * 8);
    }
    CPCOMMIT();
    {
        const __half* kr = kb + (size_t)(t0 * 64 + lr) * Dd;
        const __half* vr = vb + (size_t)(t0 * 64 + lr) * Dd;
        #pragma unroll
        for (int c = 0; c < 4; c++) {
            int cc = lc0 + c;
            u32 doff = lr * 128 + ((cc ^ (lr & 7)) << 4);
            CP16(sK0 + doff, kr + cc * 8);
            CP16(sV0 + doff, vr + cc * 8);
        }
        CPCOMMIT();
    }
    asm volatile("cp.async.wait_group 0;");
    __syncthreads();

    u32 qf[4][4];
    #pragma unroll
    for (int ks = 0; ks < 4; ks++) {
        int rr = wid * 16 + ((lane >> 3) & 1) * 8 + (lane & 7);
        int cc = ks * 2 + (lane >> 4);
        u32 addr = sQ + rr * 128 + ((cc ^ (rr & 7)) << 4);
        asm volatile(
            "ldmatrix.sync.aligned.m8n8.x4.shared.b16 {%0,%1,%2,%3}, [%4];"
            : "=r"(qf[ks][0]), "=r"(qf[ks][1]), "=r"(qf[ks][2]), "=r"(qf[ks][3])
            : "r"(addr));
    }

    float m0 = -3.4e38f, m1 = -3.4e38f, l0 = 0.f, l1 = 0.f;
    float oacc[8][4];
    #pragma unroll
    for (int nt = 0; nt < 8; nt++)
        #pragma unroll
        for (int e = 0; e < 4; e++) oacc[nt][e] = 0.f;

    const int qr = lane >> 2;
    const int qc2 = (lane & 3) << 1;

    for (int t = t0; t <= t1; t++) {
        int buf = (t - t0) & 1;
        if (t < t1) {
            u32 off = (buf ^ 1) * 8192;
            const __half* kr = kb + (size_t)((t + 1) * 64 + lr) * Dd;
            const __half* vr = vb + (size_t)((t + 1) * 64 + lr) * Dd;
            #pragma unroll
            for (int c = 0; c < 4; c++) {
                int cc = lc0 + c;
                u32 doff = lr * 128 + ((cc ^ (lr & 7)) << 4);
                CP16(sK0 + off + doff, kr + cc * 8);
                CP16(sV0 + off + doff, vr + cc * 8);
            }
            CPCOMMIT();
            asm volatile("cp.async.wait_group 1;");
        } else {
            asm volatile("cp.async.wait_group 0;");
        }
        __syncthreads();

        const u32 sK = sK0 + buf * 8192;
        const u32 sV = sV0 + buf * 8192;

        float sacc[8][4];
        #pragma unroll
        for (int nt = 0; nt < 8; nt++) {
            sacc[nt][0] = sacc[nt][1] = sacc[nt][2] = sacc[nt][3] = 0.f;
            #pragma unroll
            for (int ks = 0; ks < 4; ks++) {
                int krow = nt * 8 + (lane & 7);
                int cc = ks * 2 + ((lane >> 3) & 1);
                u32 addr = sK + krow * 128 + ((cc ^ (krow & 7)) << 4);
                u32 bf0, bf1;
                asm volatile(
                    "ldmatrix.sync.aligned.m8n8.x2.shared.b16 {%0,%1}, [%2];"
                    : "=r"(bf0), "=r"(bf1) : "r"(addr));
                asm volatile(
                    "mma.sync.aligned.m16n8k16.row.col.f32.f16.f16.f32 "
                    "{%0,%1,%2,%3}, {%4,%5,%6,%7}, {%8,%9}, {%0,%1,%2,%3};"
                    : "+f"(sacc[nt][0]), "+f"(sacc[nt][1]),
                      "+f"(sacc[nt][2]), "+f"(sacc[nt][3])
                    : "r"(qf[ks][0]), "r"(qf[ks][1]), "r"(qf[ks][2]), "r"(qf[ks][3]),
                      "r"(bf0), "r"(bf1));
            }
        }

        float mt0 = -3.4e38f, mt1 = -3.4e38f;
        #pragma unroll
        for (int nt = 0; nt < 8; nt++) {
            #pragma unroll
            for (int e = 0; e < 4; e++) {
                float s = sacc[nt][e] * 0.125f;
                if (WINDOWED) {
                    int i = q0 + wid * 16 + qr + ((e >> 1) << 3);
                    int j = t * 64 + nt * 8 + qc2 + (e & 1);
                    s += slope * (float)(j - i);
                    if (j > i || (i - j) >= WINW) s = -3.4e38f;
                }
                sacc[nt][e] = s;
                if (e < 2) mt0 = fmaxf(mt0, s); else mt1 = fmaxf(mt1, s);
            }
        }
        mt0 = fmaxf(mt0, __shfl_xor_sync(0xffffffffu, mt0, 1));
        mt0 = fmaxf(mt0, __shfl_xor_sync(0xffffffffu, mt0, 2));
        mt1 = fmaxf(mt1, __shfl_xor_sync(0xffffffffu, mt1, 1));
        mt1 = fmaxf(mt1, __shfl_xor_sync(0xffffffffu, mt1, 2));

        float mn0 = fmaxf(m0, mt0), mn1 = fmaxf(m1, mt1);
        bool dead0 = mn0 < -1e37f, dead1 = mn1 < -1e37f;
        float corr0 = dead0 ? 1.f : __expf(m0 - mn0);
        float corr1 = dead1 ? 1.f : __expf(m1 - mn1);

        float ls0 = 0.f, ls1 = 0.f;
        #pragma unroll
        for (int nt = 0; nt < 8; nt++) {
            float p0 = dead0 ? 0.f : __expf(sacc[nt][0] - mn0);
            float p1 = dead0 ? 0.f : __expf(sacc[nt][1] - mn0);
            float p2 = dead1 ? 0.f : __expf(sacc[nt][2] - mn1);
            float p3 = dead1 ? 0.f : __expf(sacc[nt][3] - mn1);
            sacc[nt][0] = p0; sacc[nt][1] = p1; sacc[nt][2] = p2; sacc[nt][3] = p3;
            ls0 += p0 + p1; ls1 += p2 + p3;
        }
        ls0 += __shfl_xor_sync(0xffffffffu, ls0, 1);
        ls0 += __shfl_xor_sync(0xffffffffu, ls0, 2);
        ls1 += __shfl_xor_sync(0xffffffffu, ls1, 1);
        ls1 += __shfl_xor_sync(0xffffffffu, ls1, 2);

        l0 = l0 * corr0 + ls0;
        l1 = l1 * corr1 + ls1;
        m0 = mn0; m1 = mn1;

        #pragma unroll
        for (int nt = 0; nt < 8; nt++) {
            oacc[nt][0] *= corr0; oacc[nt][1] *= corr0;
            oacc[nt][2] *= corr1; oacc[nt][3] *= corr1;
        }

        #pragma unroll
        for (int ks = 0; ks < 4; ks++) {
            __half2 ph0 = __floats2half2_rn(sacc[2*ks][0], sacc[2*ks][1]);
            __half2 ph1 = __floats2half2_rn(sacc[2*ks][2], sacc[2*ks][3]);
            __half2 ph2 = __floats2half2_rn(sacc[2*ks+1][0], sacc[2*ks+1][1]);
            __half2 ph3 = __floats2half2_rn(sacc[2*ks+1][2], sacc[2*ks+1][3]);
            u32 pa0 = *(u32*)&ph0, pa1 = *(u32*)&ph1;
            u32 pa2 = *(u32*)&ph2, pa3 = *(u32*)&ph3;
            #pragma unroll
            for (int nt = 0; nt < 8; nt++) {
                int vrow = ks * 16 + (lane & 15);
                u32 addr = sV + vrow * 128 + ((nt ^ (vrow & 7)) << 4);
                u32 vf0, vf1;
                asm volatile(
                    "ldmatrix.sync.aligned.m8n8.x2.trans.shared.b16 {%0,%1}, [%2];"
                    : "=r"(vf0), "=r"(vf1) : "r"(addr));
                asm volatile(
                    "mma.sync.aligned.m16n8k16.row.col.f32.f16.f16.f32 "
                    "{%0,%1,%2,%3}, {%4,%5,%6,%7}, {%8,%9}, {%0,%1,%2,%3};"
                    : "+f"(oacc[nt][0]), "+f"(oacc[nt][1]),
                      "+f"(oacc[nt][2]), "+f"(oacc[nt][3])
                    : "r"(pa0), "r"(pa1), "r"(pa2), "r"(pa3),
                      "r"(vf0), "r"(vf1));
            }
        }
        __syncthreads();
    }

    float inv0 = 1.0f / l0, inv1 = 1.0f / l1;
    int row_lo = q0 + wid * 16 + qr;
    __half* ob = out + (size_t)(b * Ll) * Dd + h * DHh;
    #pragma unroll
    for (int nt = 0; nt < 8; nt++) {
        __half2 h0 = __floats2half2_rn(oacc[nt][0] * inv0, oacc[nt][1] * inv0);
        __half2 h1 = __floats2half2_rn(oacc[nt][2] * inv1, oacc[nt][3] * inv1);
        *(__half2*)(ob + (size_t)row_lo * Dd + nt * 8 + qc2) = h0;
        *(__half2*)(ob + (size_t)(row_lo + 8) * Dd + nt * 8 + qc2) = h1;
    }
}

// ---------------------------------------------------------------------------
// out = LayerNorm(a + bres) * g + be. Optional fp16 mirror.
// ---------------------------------------------------------------------------
__global__ __launch_bounds__(256) void add_ln_kernel(
    const float* __restrict__ a, const float* __restrict__ bres,
    const float* __restrict__ g, const float* __restrict__ be,
    float* __restrict__ out, __half* __restrict__ out16)
{
    const int row = blockIdx.x;
    const int tid = threadIdx.x;
    const int d4 = tid << 2;

    float4 va = *(const float4*)(a + (size_t)row * Dd + d4);
    float4 vb = *(const float4*)(bres + (size_t)row * Dd + d4);
    float x0 = va.x + vb.x, x1 = va.y + vb.y, x2 = va.z + vb.z, x3 = va.w + vb.w;

    float s = x0 + x1 + x2 + x3;
    float ss = x0 * x0 + x1 * x1 + x2 * x2 + x3 * x3;

    #pragma unroll
    for (int off = 16; off >= 1; off >>= 1) {
        s  += __shfl_down_sync(0xffffffffu, s,  off);
        ss += __shfl_down_sync(0xffffffffu, ss, off);
    }
    __shared__ float rs[8], rss[8];
    __shared__ float s_mu, s_rstd;
    if ((tid & 31) == 0) { rs[tid >> 5] = s; rss[tid >> 5] = ss; }
    __syncthreads();
    if (tid == 0) {
        float S = 0.f, SS = 0.f;
        #pragma unroll
        for (int w = 0; w < 8; w++) { S += rs[w]; SS += rss[w]; }
        float mu = S * (1.0f / Dd);
        float var = SS * (1.0f / Dd) - mu * mu;
        s_mu = mu;
        s_rstd = rsqrtf(var + 1e-5f);
    }
    __syncthreads();
    float mu = s_mu, rstd = s_rstd;

    float4 gg = *(const float4*)(g + d4);
    float4 bb = *(const float4*)(be + d4);
    float4 o;
    o.x = (x0 - mu) * rstd * gg.x + bb.x;
    o.y = (x1 - mu) * rstd * gg.y + bb.y;
    o.z = (x2 - mu) * rstd * gg.z + bb.z;
    o.w = (x3 - mu) * rstd * gg.w + bb.w;
    *(float4*)(out + (size_t)row * Dd + d4) = o;
    if (out16) {
        __half2 h0 = __floats2half2_rn(o.x, o.y);
        __half2 h1 = __floats2half2_rn(o.z, o.w);
        uint2 ho; ho.x = *(u32*)&h0; ho.y = *(u32*)&h1;
        *(uint2*)(out16 + (size_t)row * Dd + d4) = ho;
    }
}

// ---------------------------------------------------------------------------
extern "C" void kernel_launch(void* const* d_in, const int* in_sizes, int n_in,
                              void* d_out, int out_size)
{
    const float* x   = (const float*)d_in[0];
    const float* mem = (const float*)d_in[1];

    const float *swq, *sbq, *swk, *sbk, *swv, *sbv, *swo, *sbo;
    const float *cwq, *cbq, *cwk, *cbk, *cwv, *cbv, *cwo, *cbo;
    const float *w1, *b1, *w2, *b2, *g1, *be1, *g2, *be2, *g3, *be3;

    if (in_sizes[3] == Dd) {
        swq=(const float*)d_in[2];  sbq=(const float*)d_in[3];
        swk=(const float*)d_in[4];  sbk=(const float*)d_in[5];
        swv=(const float*)d_in[6];  sbv=(const float*)d_in[7];
        swo=(const float*)d_in[8];  sbo=(const float*)d_in[9];
        cwq=(const float*)d_in[10]; cbq=(const float*)d_in[11];
        cwk=(const float*)d_in[12]; cbk=(const float*)d_in[13];
        cwv=(const float*)d_in[14]; cbv=(const float*)d_in[15];
        cwo=(const float*)d_in[16]; cbo=(const float*)d_in[17];
        w1=(const float*)d_in[18];  b1=(const float*)d_in[19];
        w2=(const float*)d_in[20];  b2=(const float*)d_in[21];
        g1=(const float*)d_in[22];  be1=(const float*)d_in[23];
        g2=(const float*)d_in[24];  be2=(const float*)d_in[25];
        g3=(const float*)d_in[26];  be3=(const float*)d_in[27];
    } else {
        swq=(const float*)d_in[2];  swk=(const float*)d_in[3];
        swv=(const float*)d_in[4];  swo=(const float*)d_in[5];
        sbq=(const float*)d_in[6];  sbk=(const float*)d_in[7];
        sbv=(const float*)d_in[8];  sbo=(const float*)d_in[9];
        cwq=(const float*)d_in[10]; cwk=(const float*)d_in[11];
        cwv=(const float*)d_in[12]; cwo=(const float*)d_in[13];
        cbq=(const float*)d_in[14]; cbk=(const float*)d_in[15];
        cbv=(const float*)d_in[16]; cbo=(const float*)d_in[17];
        w1=(const float*)d_in[18];  b1=(const float*)d_in[19];
        w2=(const float*)d_in[20];  b2=(const float*)d_in[21];
        g1=(const float*)d_in[22];  g2=(const float*)d_in[23];
        g3=(const float*)d_in[24];
        be1=(const float*)d_in[25]; be2=(const float*)d_in[26];
        be3=(const float*)d_in[27];
    }

    float* s32 = nullptr;
    cudaGetSymbolAddress((void**)&s32, g_f32);
    __half* s16 = nullptr;
    cudaGetSymbolAddress((void**)&s16, g_f16);

    float* btmp = s32;
    float* bx1  = s32 + (size_t)SEG;
    float* bx2  = s32 + (size_t)SEG * 2;

    __half* x16    = s16;
    __half* mem16  = s16 + (size_t)4*M1;
    __half* wq16   = s16 + (size_t)8*M1;
    __half* wk16   = s16 + (size_t)9*M1;
    __half* wv16   = s16 + (size_t)10*M1;
    __half* wo16   = s16 + (size_t)11*M1;
    __half* cq16   = s16 + (size_t)12*M1;
    __half* ck16   = s16 + (size_t)13*M1;
    __half* cv16   = s16 + (size_t)14*M1;
    __half* co16   = s16 + (size_t)15*M1;
    __half* w1_16  = s16 + (size_t)16*M1;
    __half* w2_16  = s16 + (size_t)20*M1;
    __half* bq16   = s16 + (size_t)24*M1;
    __half* bk16   = s16 + (size_t)28*M1;
    __half* bv16   = s16 + (size_t)32*M1;
    __half* batt16 = s16 + (size_t)36*M1;
    __half* bx1_16 = s16 + (size_t)40*M1;
    __half* bx2_16 = s16 + (size_t)44*M1;
    __half* bff16  = s16 + (size_t)48*M1;

    CvtArgs ca;
    ca.job[0]  = { x,   x16,   4*M1 };
    ca.job[1]  = { mem, mem16, 4*M1 };
    ca.job[2]  = { swq, wq16,  M1 };
    ca.job[3]  = { swk, wk16,  M1 };
    ca.job[4]  = { swv, wv16,  M1 };
    ca.job[5]  = { swo, wo16,  M1 };
    ca.job[6]  = { cwq, cq16,  M1 };
    ca.job[7]  = { cwk, ck16,  M1 };
    ca.job[8]  = { cwv, cv16,  M1 };
    ca.job[9]  = { cwo, co16,  M1 };
    ca.job[10] = { w1,  w1_16, 4*M1 };
    ca.job[11] = { w2,  w2_16, 4*M1 };
    dim3 gCvt(512, 12);
    cvt_kernel<<<gCvt, 256>>>(ca);

    dim3 gP(Dd / 128, RB / 128);
    dim3 gF1(FFf / 128, RB / 128);
    dim3 gAttn(Ll / 64, Bb * Hh);

    // ---- self-attention ----
    hgemm16_kernel<false><<<gP, 256>>>(x16, wq16, sbq, nullptr, bq16, Dd, Dd);
    hgemm16_kernel<false><<<gP, 256>>>(x16, wk16, sbk, nullptr, bk16, Dd, Dd);
    hgemm16_kernel<false><<<gP, 256>>>(x16, wv16, sbv, nullptr, bv16, Dd, Dd);
    attn_mma_kernel<true><<<gAttn, 128>>>(bq16, bk16, bv16, batt16, Ll);
    hgemm16_kernel<false><<<gP, 256>>>(batt16, wo16, sbo, btmp, nullptr, Dd, Dd);
    add_ln_kernel<<<RB, 256>>>(x, btmp, g1, be1, bx1, bx1_16);

    // ---- cross-attention ----
    hgemm16_kernel<false><<<gP, 256>>>(bx1_16, cq16, cbq, nullptr, bq16, Dd, Dd);
    hgemm16_kernel<false><<<gP, 256>>>(mem16, ck16, cbk, nullptr, bk16, Dd, Dd);
    hgemm16_kernel<false><<<gP, 256>>>(mem16, cv16, cbv, nullptr, bv16, Dd, Dd);
    attn_mma_kernel<false><<<gAttn, 128>>>(bq16, bk16, bv16, batt16, Mm);
    hgemm16_kernel<false><<<gP, 256>>>(batt16, co16, cbo, btmp, nullptr, Dd, Dd);
    add_ln_kernel<<<RB, 256>>>(bx1, btmp, g2, be2, bx2, bx2_16);

    // ---- FFN ----
    hgemm16_kernel<true><<<gF1, 256>>>(bx2_16, w1_16, b1, nullptr, bff16, Dd, FFf);
    hgemm16_kernel<false><<<gP, 256>>>(bff16, w2_16, b2, btmp, nullptr, FFf, Dd);
    add_ln_kernel<<<RB, 256>>>(bx2, btmp, g3, be3, (float*)d_out, nullptr);
}